// round 2
// baseline (speedup 1.0000x reference)
#include <cuda_runtime.h>
#include <math.h>

// Problem constants
#define NPROTO 256
#define NCH    256
#define NHW    4096
#define NBATCH 32
#define NT     64      // pixels per block tile
#define KT     32      // k (channel) chunk
#define ASTR   266     // padded smem row stride for A tile (protos)
#define QSTR   160     // Q dup tile row stride: 8 groups * 20 floats

// Scratch (static device globals — no allocation)
__device__ float g_protosN[NPROTO * NCH];
__device__ int   g_valid[NPROTO];

// ---------------------------------------------------------------------------
// Kernel 1: build normalized prototypes + validity mask.
// One block per proto p = s*64 + i*8 + j ; thread c = channel.
// ---------------------------------------------------------------------------
__global__ void proto_kernel(const float* __restrict__ sup_x,
                             const float* __restrict__ sup_y) {
    __shared__ float sh[256];
    int p = blockIdx.x;
    int s = p >> 6, ij = p & 63, i = ij >> 3, j = ij & 7;
    int c = threadIdx.x;

    const float* base = sup_x + (((size_t)(s * 256 + c)) * 64 + i * 8) * 64 + j * 8;
    float sum = 0.f;
#pragma unroll
    for (int di = 0; di < 8; di++) {
        const float4* r = (const float4*)(base + di * 64);
        float4 a = r[0], b4 = r[1];
        sum += ((a.x + a.y) + (a.z + a.w)) + ((b4.x + b4.y) + (b4.z + b4.w));
    }
    float f = sum * (1.0f / 64.0f);

    // norm over channels
    sh[c] = f * f;
    __syncthreads();
    for (int st = 128; st > 0; st >>= 1) {
        if (c < st) sh[c] += sh[c + st];
        __syncthreads();
    }
    float nrm = sqrtf(sh[0]);
    float inv = 1.0f / fmaxf(nrm, 1e-4f);
    g_protosN[p * NCH + c] = f * inv;
    __syncthreads();

    // validity: mean of binary mask over the 8x8 block > 0.5
    float m = 0.f;
    if (c < 64) {
        int di = c >> 3, dj = c & 7;
        float y = sup_y[(size_t)s * 4096 + (i * 8 + di) * 64 + (j * 8 + dj)];
        m = (y > 0.95f) ? 1.f : 0.f;
    }
    sh[c] = m;
    __syncthreads();
    for (int st = 128; st > 0; st >>= 1) {
        if (c < st) sh[c] += sh[c + st];
        __syncthreads();
    }
    if (c == 0) g_valid[p] = (sh[0] * (1.0f / 64.0f) > 0.5f) ? 1 : 0;
}

// ---------------------------------------------------------------------------
// Kernel 2: proto_grid passthrough (output segment 3)
// ---------------------------------------------------------------------------
__global__ void grid_kernel(const float* __restrict__ sup_y, float* __restrict__ out) {
    int idx = blockIdx.x * 256 + threadIdx.x;
    if (idx < 16384)
        out[262144 + idx] = (sup_y[idx] > 0.95f) ? 1.f : 0.f;
}

// ---------------------------------------------------------------------------
// Packed f32x2 FMA (PTX-only path; ptxas never auto-fuses this)
// ---------------------------------------------------------------------------
__device__ __forceinline__ void ffma2(unsigned long long& d,
                                      unsigned long long a,
                                      unsigned long long b) {
    asm("fma.rn.f32x2 %0, %1, %2, %0;" : "+l"(d) : "l"(a), "l"(b));
}

// ---------------------------------------------------------------------------
// Kernel 3: fused GEMM + norm + masked softmax + argmax + pred
// grid = 32 batches * 64 pixel tiles ; block = 256 threads
// thread (ty,tx): protos [ty*8, ty*8+8) as 4 packed pairs; pixels [tx*8, tx*8+8)
// ---------------------------------------------------------------------------
__global__ void __launch_bounds__(256, 2)
dist_kernel(const float* __restrict__ qry, float* __restrict__ out) {
    extern __shared__ float sm[];
    float* As = sm;                     // KT * ASTR = 8512 floats
    float* Qs = sm + KT * ASTR;         // KT * QSTR = 5120 floats (dup'd q)
    float* dS = sm;                     // reused: 256*64 = 16384 floats
    float* ssq = sm + NPROTO * NT;      // 4*64 partial sum-of-squares
    float* gN  = ssq + 256;             // 64 qnorms
    float* rA  = gN + 64;               // 4*64 partial max
    int*   rI  = (int*)(rA + 256);      // 4*64 partial argmax
    float* rS  = (float*)(rI + 256);    // 4*64 partial sumexp
    float* rW  = rS + 256;              // 4*64 partial weighted sum
    float* gM  = rW + 256;              // 64 global max
    int*   gI  = (int*)(gM + 64);       // 64 global argmax

    int tid = threadIdx.x;
    int b  = blockIdx.x >> 6;
    int n0 = (blockIdx.x & 63) << 6;
    const float* Qb = qry + (size_t)b * NCH * NHW + n0;

    int ty = tid >> 3, tx = tid & 7;    // compute mapping
    int ln = tid & 63, lk = tid >> 6;   // load/reduce mapping

    unsigned long long acc[4][8];
#pragma unroll
    for (int a = 0; a < 4; a++)
#pragma unroll
        for (int nn = 0; nn < 8; nn++) acc[a][nn] = 0ull;

    float myssq = 0.f;
    const int qgrp = (ln >> 3) * 20 + (ln & 7) * 2;   // dup slot for pixel ln

    for (int ct = 0; ct < 8; ct++) {
        int c0 = ct * KT;
        __syncthreads();
        // Load A tile: As[kk][p] = protosN[p][c0+kk]  (coalesced on kk)
#pragma unroll 8
        for (int i = 0; i < 32; i++) {
            int f = tid + i * 256;
            int kk = f & 31, p = f >> 5;
            As[kk * ASTR + p] = g_protosN[p * NCH + c0 + kk];
        }
        // Load Q tile (duplicated pairs) + accumulate sum of squares
#pragma unroll
        for (int r = 0; r < 8; r++) {
            int k = lk + (r << 2);
            float v = Qb[(size_t)(c0 + k) * NHW + ln];
            myssq += v * v;
            float* q = &Qs[k * QSTR + qgrp];
            q[0] = v; q[1] = v;
        }
        __syncthreads();

        // Compute: 32 packed FMAs per k-step per thread
#pragma unroll 4
        for (int kk = 0; kk < KT; kk++) {
            const unsigned long long* ap =
                (const unsigned long long*)&As[kk * ASTR + ty * 8];
            unsigned long long aa0 = ap[0], aa1 = ap[1], aa2 = ap[2], aa3 = ap[3];
            const ulonglong2* qp = (const ulonglong2*)&Qs[kk * QSTR + tx * 20];
            ulonglong2 u0 = qp[0], u1 = qp[1], u2 = qp[2], u3 = qp[3];
            unsigned long long qd0 = u0.x, qd1 = u0.y, qd2 = u1.x, qd3 = u1.y;
            unsigned long long qd4 = u2.x, qd5 = u2.y, qd6 = u3.x, qd7 = u3.y;

            ffma2(acc[0][0], aa0, qd0); ffma2(acc[0][1], aa0, qd1);
            ffma2(acc[0][2], aa0, qd2); ffma2(acc[0][3], aa0, qd3);
            ffma2(acc[0][4], aa0, qd4); ffma2(acc[0][5], aa0, qd5);
            ffma2(acc[0][6], aa0, qd6); ffma2(acc[0][7], aa0, qd7);
            ffma2(acc[1][0], aa1, qd0); ffma2(acc[1][1], aa1, qd1);
            ffma2(acc[1][2], aa1, qd2); ffma2(acc[1][3], aa1, qd3);
            ffma2(acc[1][4], aa1, qd4); ffma2(acc[1][5], aa1, qd5);
            ffma2(acc[1][6], aa1, qd6); ffma2(acc[1][7], aa1, qd7);
            ffma2(acc[2][0], aa2, qd0); ffma2(acc[2][1], aa2, qd1);
            ffma2(acc[2][2], aa2, qd2); ffma2(acc[2][3], aa2, qd3);
            ffma2(acc[2][4], aa2, qd4); ffma2(acc[2][5], aa2, qd5);
            ffma2(acc[2][6], aa2, qd6); ffma2(acc[2][7], aa2, qd7);
            ffma2(acc[3][0], aa3, qd0); ffma2(acc[3][1], aa3, qd1);
            ffma2(acc[3][2], aa3, qd2); ffma2(acc[3][3], aa3, qd3);
            ffma2(acc[3][4], aa3, qd4); ffma2(acc[3][5], aa3, qd5);
            ffma2(acc[3][6], aa3, qd6); ffma2(acc[3][7], aa3, qd7);
        }
    }

    // ---- qnorm reduction ----
    __syncthreads();
    ssq[lk * 64 + ln] = myssq;
    __syncthreads();
    if (tid < 64) {
        float s2 = ssq[tid] + ssq[64 + tid] + ssq[128 + tid] + ssq[192 + tid];
        gN[tid] = fmaxf(sqrtf(s2), 1e-4f);
    }
    __syncthreads();

    const float NEG = __int_as_float(0xff800000);  // -inf

    float invn[8];
#pragma unroll
    for (int nn = 0; nn < 8; nn++) invn[nn] = 20.0f / gN[tx * 8 + nn];

    // ---- scale + mask, write dists tile to smem (overwrites As/Qs) ----
#pragma unroll
    for (int pp = 0; pp < 4; pp++) {
        int p = ty * 8 + pp * 2;
        int v0 = g_valid[p], v1 = g_valid[p + 1];
#pragma unroll
        for (int nn = 0; nn < 8; nn++) {
            unsigned long long v = acc[pp][nn];
            float lo = __uint_as_float((unsigned)v);
            float hi = __uint_as_float((unsigned)(v >> 32));
            int nl = tx * 8 + nn;
            dS[p * 64 + nl]       = v0 ? lo * invn[nn] : NEG;
            dS[(p + 1) * 64 + nl] = v1 ? hi * invn[nn] : NEG;
        }
    }
    __syncthreads();

    // ---- pass 1: max + argmax (first-index tie-break, matches jnp.argmax) ----
    int n = ln, qt = lk;
    float best = NEG; int bidx = qt * 64;
#pragma unroll 8
    for (int p = qt * 64; p < qt * 64 + 64; p++) {
        float d = dS[p * 64 + n];
        if (d > best) { best = d; bidx = p; }
    }
    rA[qt * 64 + n] = best; rI[qt * 64 + n] = bidx;
    __syncthreads();
    if (tid < 64) {
        float gb = NEG; int gi = 0;
#pragma unroll
        for (int q = 0; q < 4; q++) {
            float v = rA[q * 64 + tid];
            if (v > gb) { gb = v; gi = rI[q * 64 + tid]; }
        }
        gM[tid] = gb; gI[tid] = gi;
    }
    __syncthreads();

    // ---- pass 2: sumexp + weighted sum over valid protos ----
    float mx = gM[n];
    float se = 0.f, ws = 0.f;
#pragma unroll 8
    for (int p = qt * 64; p < qt * 64 + 64; p++) {
        float d = dS[p * 64 + n];
        if (d != NEG) { float e = expf(d - mx); se += e; ws = fmaf(e, d, ws); }
    }
    rS[qt * 64 + n] = se; rW[qt * 64 + n] = ws;
    __syncthreads();
    if (tid < 64) {
        float SE = rS[tid] + rS[64 + tid] + rS[128 + tid] + rS[192 + tid];
        float WS = rW[tid] + rW[64 + tid] + rW[128 + tid] + rW[192 + tid];
        size_t o = (size_t)b * NHW + n0 + tid;
        out[o]          = WS / SE;              // pred
        out[131072 + o] = (float)gI[tid];       // debug_assign
    }
}

// ---------------------------------------------------------------------------
// launch
// ---------------------------------------------------------------------------
#define SMEM_BYTES ((256 * 64 + 256 + 64 + 256 + 256 + 256 + 256 + 64 + 64) * 4)

extern "C" void kernel_launch(void* const* d_in, const int* in_sizes, int n_in,
                              void* d_out, int out_size) {
    const float* qry   = (const float*)d_in[0];
    const float* sup_x = (const float*)d_in[1];
    const float* sup_y = (const float*)d_in[2];
    float* out = (float*)d_out;

    cudaFuncSetAttribute(dist_kernel,
                         cudaFuncAttributeMaxDynamicSharedMemorySize, SMEM_BYTES);

    proto_kernel<<<256, 256>>>(sup_x, sup_y);
    grid_kernel<<<64, 256>>>(sup_y, out);
    dist_kernel<<<NBATCH * 64, 256, SMEM_BYTES>>>(qry, out);
}

// round 4
// speedup vs baseline: 1.2274x; 1.2274x over previous
#include <cuda_runtime.h>
#include <cstdint>
#include <math.h>

// Pre-split prototypes (tf32 hi/lo), chunk-major contiguous:
// g_protoH[ct*8192 + kk*256 + p] = hi(protoN[p][ct*32+kk])
__device__ __align__(16) float g_protoH[8 * 8192];
__device__ __align__(16) float g_protoL[8 * 8192];
__device__ int g_valid[256];

// ---- smem layout (floats) ----
#define AS   260          // A tile row stride (32 rows x 260)
#define QS   68           // Q tile row stride (32 rows x 68)
#define DSS  268          // dS row stride (64 rows x 268)
#define OFF_A0  0
#define OFF_A1  16640     // 2*8320
#define OFF_QH  33280
#define OFF_QL  35456
#define OFF_SQ  37632     // 16x64
#define OFF_QN  38656     // 64
#define OFF_VM  38720     // 8 u32
#define OFF_RA  38728
#define OFF_RI  38984
#define OFF_RS  39240
#define OFF_RW  39496
#define SMEM_FLOATS 39752
#define SMEM_BYTES (SMEM_FLOATS * 4)

__device__ __forceinline__ float to_tf32(float x) {
    float r; asm("cvt.rna.tf32.f32 %0, %1;" : "=f"(r) : "f"(x)); return r;
}
__device__ __forceinline__ uint32_t s2u(const void* p) {
    uint32_t a;
    asm("{ .reg .u64 t; cvta.to.shared.u64 t, %1; cvt.u32.u64 %0, t; }"
        : "=r"(a) : "l"(p));
    return a;
}
__device__ __forceinline__ void cpasync16(uint32_t dst, const float* src) {
    size_t g = __cvta_generic_to_global((const void*)src);
    asm volatile("cp.async.cg.shared.global [%0], [%1], 16;"
                 :: "r"(dst), "l"(g) : "memory");
}
__device__ __forceinline__ void mma8(float* c, uint32_t a0, uint32_t a1,
                                     uint32_t a2, uint32_t a3,
                                     uint32_t b0, uint32_t b1) {
    asm volatile(
        "mma.sync.aligned.m16n8k8.row.col.f32.tf32.tf32.f32 "
        "{%0,%1,%2,%3}, {%4,%5,%6,%7}, {%8,%9}, {%0,%1,%2,%3};"
        : "+f"(c[0]), "+f"(c[1]), "+f"(c[2]), "+f"(c[3])
        : "r"(a0), "r"(a1), "r"(a2), "r"(a3), "r"(b0), "r"(b1));
}

// ---------------------------------------------------------------------------
// Kernel 1: prototypes -> normalized, tf32 split, chunk-major + validity
// ---------------------------------------------------------------------------
__global__ void proto_kernel(const float* __restrict__ sup_x,
                             const float* __restrict__ sup_y) {
    __shared__ float sh[256];
    int p = blockIdx.x;
    int s = p >> 6, ij = p & 63, i = ij >> 3, j = ij & 7;
    int c = threadIdx.x;

    const float* base = sup_x + (((size_t)(s * 256 + c)) * 64 + i * 8) * 64 + j * 8;
    float sum = 0.f;
#pragma unroll
    for (int di = 0; di < 8; di++) {
        const float4* r = (const float4*)(base + di * 64);
        float4 a = r[0], b4 = r[1];
        sum += ((a.x + a.y) + (a.z + a.w)) + ((b4.x + b4.y) + (b4.z + b4.w));
    }
    float f = sum * (1.0f / 64.0f);

    sh[c] = f * f;
    __syncthreads();
    for (int st = 128; st > 0; st >>= 1) {
        if (c < st) sh[c] += sh[c + st];
        __syncthreads();
    }
    float inv = 1.0f / fmaxf(sqrtf(sh[0]), 1e-4f);
    float v = f * inv;
    float vh = to_tf32(v), vl = to_tf32(v - vh);
    int ct = c >> 5, kk = c & 31;
    g_protoH[ct * 8192 + kk * 256 + p] = vh;
    g_protoL[ct * 8192 + kk * 256 + p] = vl;
    __syncthreads();

    float m = 0.f;
    if (c < 64) {
        int di = c >> 3, dj = c & 7;
        float y = sup_y[(size_t)s * 4096 + (i * 8 + di) * 64 + (j * 8 + dj)];
        m = (y > 0.95f) ? 1.f : 0.f;
    }
    sh[c] = m;
    __syncthreads();
    for (int st = 128; st > 0; st >>= 1) {
        if (c < st) sh[c] += sh[c + st];
        __syncthreads();
    }
    if (c == 0) g_valid[p] = (sh[0] * (1.0f / 64.0f) > 0.5f) ? 1 : 0;
}

__global__ void grid_kernel(const float* __restrict__ sup_y, float* __restrict__ out) {
    int idx = blockIdx.x * 256 + threadIdx.x;
    if (idx < 16384)
        out[262144 + idx] = (sup_y[idx] > 0.95f) ? 1.f : 0.f;
}

// ---------------------------------------------------------------------------
// Kernel 3: 3xTF32 mma.sync GEMM + fused masked softmax / argmax / pred
// grid = 32 batches * 64 tiles(64 px) ; 256 threads, 8 warps (4 wm x 2 wn)
// ---------------------------------------------------------------------------
__global__ void __launch_bounds__(256, 1)
dist_kernel(const float* __restrict__ qry, float* __restrict__ out) {
    extern __shared__ __align__(16) float sm[];
    float* QH = sm + OFF_QH;
    float* QL = sm + OFF_QL;
    float* SQ = sm + OFF_SQ;
    float* QN = sm + OFF_QN;
    uint32_t* VM = (uint32_t*)(sm + OFF_VM);
    float* RA = sm + OFF_RA;
    int*   RI = (int*)(sm + OFF_RI);
    float* RS = sm + OFF_RS;
    float* RW = sm + OFF_RW;

    int tid = threadIdx.x, w = tid >> 5, l = tid & 31;
    int wm = w & 3, wn = w >> 2;

    unsigned bal = __ballot_sync(0xffffffffu, g_valid[tid] != 0);
    if (l == 0) VM[w] = bal;

    int b = blockIdx.x >> 6, n0 = (blockIdx.x & 63) << 6;
    const float* Qbase = qry + (size_t)b * 256 * 4096 + n0;

    float acc[4][4][4];
#pragma unroll
    for (int tm = 0; tm < 4; tm++)
#pragma unroll
        for (int tn = 0; tn < 4; tn++)
#pragma unroll
            for (int e = 0; e < 4; e++) acc[tm][tn][e] = 0.f;

    float4 qv0, qv1;
    float4 ssq4 = make_float4(0.f, 0.f, 0.f, 0.f);
    const int kk0 = tid >> 4, nf = tid & 15;

    // ---- prologue: chunk 0 A cp.async + Q regs ----
    {
        const float* sH = g_protoH;
        const float* sL = g_protoL;
#pragma unroll
        for (int i = 0; i < 8; i++) {
            int seg = tid + i * 256;
            int row = seg >> 6, col = (seg & 63) << 2;
            cpasync16(s2u(sm + OFF_A0 + row * AS + col), sH + row * 256 + col);
            cpasync16(s2u(sm + OFF_A0 + 8320 + row * AS + col), sL + row * 256 + col);
        }
        asm volatile("cp.async.commit_group;" ::: "memory");
        qv0 = *(const float4*)(Qbase + (size_t)kk0 * 4096 + nf * 4);
        qv1 = *(const float4*)(Qbase + (size_t)(kk0 + 16) * 4096 + nf * 4);
    }

    const int ka = l & 3, ga = l >> 2;

    for (int ct = 0; ct < 8; ct++) {
        int stg = ct & 1;
        float* AH = sm + (stg ? OFF_A1 : OFF_A0);
        float* AL = AH + 8320;
        float* AHn = sm + (stg ? OFF_A0 : OFF_A1);

        if (ct < 7) {
            const float* sH = g_protoH + (ct + 1) * 8192;
            const float* sL = g_protoL + (ct + 1) * 8192;
#pragma unroll
            for (int i = 0; i < 8; i++) {
                int seg = tid + i * 256;
                int row = seg >> 6, col = (seg & 63) << 2;
                cpasync16(s2u(AHn + row * AS + col), sH + row * 256 + col);
                cpasync16(s2u(AHn + 8320 + row * AS + col), sL + row * 256 + col);
            }
            asm volatile("cp.async.commit_group;" ::: "memory");
        }

        // split + store Q (current chunk), accumulate ssq
        {
            float4 v = qv0, hv, lv;
            hv.x = to_tf32(v.x); lv.x = to_tf32(v.x - hv.x); ssq4.x = fmaf(v.x, v.x, ssq4.x);
            hv.y = to_tf32(v.y); lv.y = to_tf32(v.y - hv.y); ssq4.y = fmaf(v.y, v.y, ssq4.y);
            hv.z = to_tf32(v.z); lv.z = to_tf32(v.z - hv.z); ssq4.z = fmaf(v.z, v.z, ssq4.z);
            hv.w = to_tf32(v.w); lv.w = to_tf32(v.w - hv.w); ssq4.w = fmaf(v.w, v.w, ssq4.w);
            *(float4*)(QH + kk0 * QS + nf * 4) = hv;
            *(float4*)(QL + kk0 * QS + nf * 4) = lv;
            v = qv1;
            hv.x = to_tf32(v.x); lv.x = to_tf32(v.x - hv.x); ssq4.x = fmaf(v.x, v.x, ssq4.x);
            hv.y = to_tf32(v.y); lv.y = to_tf32(v.y - hv.y); ssq4.y = fmaf(v.y, v.y, ssq4.y);
            hv.z = to_tf32(v.z); lv.z = to_tf32(v.z - hv.z); ssq4.z = fmaf(v.z, v.z, ssq4.z);
            hv.w = to_tf32(v.w); lv.w = to_tf32(v.w - hv.w); ssq4.w = fmaf(v.w, v.w, ssq4.w);
            *(float4*)(QH + (kk0 + 16) * QS + nf * 4) = hv;
            *(float4*)(QL + (kk0 + 16) * QS + nf * 4) = lv;
        }

        if (ct < 7) asm volatile("cp.async.wait_group 1;" ::: "memory");
        else        asm volatile("cp.async.wait_group 0;" ::: "memory");
        __syncthreads();

        if (ct < 7) {
            const float* qc = Qbase + (size_t)(ct + 1) * 32 * 4096;
            qv0 = *(const float4*)(qc + (size_t)kk0 * 4096 + nf * 4);
            qv1 = *(const float4*)(qc + (size_t)(kk0 + 16) * 4096 + nf * 4);
        }

        // ---- MMA: 4 ksteps of 8 ----
#pragma unroll
        for (int ks = 0; ks < 4; ks++) {
            uint32_t bh[4][2], bl[4][2];
            const int qb = (ks * 8 + ka) * QS + wn * 32 + ga;
#pragma unroll
            for (int tn = 0; tn < 4; tn++) {
                bh[tn][0] = __float_as_uint(QH[qb + tn * 8]);
                bh[tn][1] = __float_as_uint(QH[qb + tn * 8 + 4 * QS]);
                bl[tn][0] = __float_as_uint(QL[qb + tn * 8]);
                bl[tn][1] = __float_as_uint(QL[qb + tn * 8 + 4 * QS]);
            }
            const int ab = (ks * 8 + ka) * AS + wm * 64 + ga;
#pragma unroll
            for (int tm = 0; tm < 4; tm++) {
                int a0i = ab + tm * 16;
                uint32_t ah0 = __float_as_uint(AH[a0i]);
                uint32_t ah1 = __float_as_uint(AH[a0i + 8]);
                uint32_t ah2 = __float_as_uint(AH[a0i + 4 * AS]);
                uint32_t ah3 = __float_as_uint(AH[a0i + 4 * AS + 8]);
                uint32_t al0 = __float_as_uint(AL[a0i]);
                uint32_t al1 = __float_as_uint(AL[a0i + 8]);
                uint32_t al2 = __float_as_uint(AL[a0i + 4 * AS]);
                uint32_t al3 = __float_as_uint(AL[a0i + 4 * AS + 8]);
#pragma unroll
                for (int tn = 0; tn < 4; tn++) {
                    mma8(acc[tm][tn], ah0, ah1, ah2, ah3, bh[tn][0], bh[tn][1]);
                    mma8(acc[tm][tn], ah0, ah1, ah2, ah3, bl[tn][0], bl[tn][1]);
                    mma8(acc[tm][tn], al0, al1, al2, al3, bh[tn][0], bh[tn][1]);
                }
            }
        }
        __syncthreads();
    }

    // ---- qnorm reduction (deterministic) ----
    *(float4*)(SQ + (tid >> 4) * 64 + (tid & 15) * 4) = ssq4;
    __syncthreads();
    if (tid < 64) {
        float s = 0.f;
#pragma unroll
        for (int j = 0; j < 16; j++) s += SQ[j * 64 + tid];
        QN[tid] = 20.0f / fmaxf(sqrtf(s), 1e-4f);
    }

    // ---- write dS transposed [n][p] (reuses A-stage smem) ----
    float* dS = sm;
    {
        int r0 = wm * 64 + ga;
        int nc0 = wn * 32 + 2 * ka;
#pragma unroll
        for (int tm = 0; tm < 4; tm++) {
            int r = r0 + tm * 16;
#pragma unroll
            for (int tn = 0; tn < 4; tn++) {
                int n = nc0 + tn * 8;
                dS[n * DSS + r]           = acc[tm][tn][0];
                dS[(n + 1) * DSS + r]     = acc[tm][tn][1];
                dS[n * DSS + r + 8]       = acc[tm][tn][2];
                dS[(n + 1) * DSS + r + 8] = acc[tm][tn][3];
            }
        }
    }
    __syncthreads();

    // ---- online masked softmax + argmax over proto quarters ----
    const float NEG = __int_as_float(0xff800000);
    int q = tid >> 6, n = tid & 63;
    float sc = QN[n];
    uint32_t m0 = VM[q * 2], m1 = VM[q * 2 + 1];
    float best = NEG, se = 0.f, ws = 0.f;
    int bidx = q * 64;
    const float4* row = (const float4*)(dS + n * DSS + q * 64);
#pragma unroll 4
    for (int i = 0; i < 16; i++) {
        float4 v = row[i];
        float vv[4] = {v.x, v.y, v.z, v.w};
#pragma unroll
        for (int e = 0; e < 4; e++) {
            int p = i * 4 + e;
            uint32_t ok = ((p < 32 ? m0 : m1) >> (p & 31)) & 1u;
            if (ok) {
                float d = vv[e] * sc;
                if (d > best) {
                    float rr = expf(best - d);
                    se = se * rr + 1.f; ws = ws * rr + d;
                    best = d; bidx = q * 64 + p;
                } else {
                    float e2 = expf(d - best);
                    se += e2; ws = fmaf(e2, d, ws);
                }
            }
        }
    }
    RA[q * 64 + n] = best; RI[q * 64 + n] = bidx;
    RS[q * 64 + n] = se;   RW[q * 64 + n] = ws;
    __syncthreads();

    if (tid < 64) {
        float B = NEG, SE = 0.f, WS = 0.f; int I = 0;
#pragma unroll
        for (int qq = 0; qq < 4; qq++) {
            float bq = RA[qq * 64 + tid];
            float sq = RS[qq * 64 + tid], wq = RW[qq * 64 + tid];
            if (bq > B) {
                float r = (B == NEG) ? 0.f : expf(B - bq);
                SE = SE * r + sq; WS = WS * r + wq;
                B = bq; I = RI[qq * 64 + tid];
            } else {
                float r = (bq == NEG) ? 0.f : expf(bq - B);
                SE += sq * r; WS += wq * r;
            }
        }
        size_t o = (size_t)b * 4096 + n0 + tid;
        out[o] = WS / SE;
        out[131072 + o] = (float)I;
    }
}

extern "C" void kernel_launch(void* const* d_in, const int* in_sizes, int n_in,
                              void* d_out, int out_size) {
    const float* qry   = (const float*)d_in[0];
    const float* sup_x = (const float*)d_in[1];
    const float* sup_y = (const float*)d_in[2];
    float* out = (float*)d_out;

    cudaFuncSetAttribute(dist_kernel,
                         cudaFuncAttributeMaxDynamicSharedMemorySize, SMEM_BYTES);

    proto_kernel<<<256, 256>>>(sup_x, sup_y);
    grid_kernel<<<64, 256>>>(sup_y, out);
    dist_kernel<<<2048, 256, SMEM_BYTES>>>(qry, out);
}

// round 5
// speedup vs baseline: 1.5088x; 1.2292x over previous
#include <cuda_runtime.h>
#include <cstdint>
#include <math.h>

// Pre-split prototypes (tf32 hi/lo), chunk-major contiguous:
// g_protoH[ct*4096 + kk*256 + p] = hi(protoN[p][ct*16+kk]),  ct=0..15, kk=0..15
__device__ __align__(16) float g_protoH[16 * 4096];
__device__ __align__(16) float g_protoL[16 * 4096];
__device__ int g_valid[256];

// ---- smem layout (floats) ----
#define AS   260          // A tile row stride (16 rows x 260), H then L per stage
#define QS   68           // Q tile row stride (16 rows x 68)
#define DSS  268          // dS row stride (64 rows x 268)
#define STG_FLOATS 8320   // 2 * 16 * 260  (AH | AL)
#define OFF_A0  0
#define OFF_A1  8320
#define OFF_QH  16640     // 16*68 = 1088
#define OFF_QL  17728
#define OFF_SQ  18816     // 16 x 64
#define OFF_QN  19840     // 64
#define OFF_VM  19904     // 8 u32
#define OFF_RA  19912
#define OFF_RI  20168
#define OFF_RS  20424
#define OFF_RW  20680
#define SMEM_FLOATS 20936
#define SMEM_BYTES (SMEM_FLOATS * 4)   // ~83.7 KB -> 2 CTAs/SM

__device__ __forceinline__ float to_tf32(float x) {
    float r; asm("cvt.rna.tf32.f32 %0, %1;" : "=f"(r) : "f"(x)); return r;
}
__device__ __forceinline__ uint32_t s2u(const void* p) {
    uint32_t a;
    asm("{ .reg .u64 t; cvta.to.shared.u64 t, %1; cvt.u32.u64 %0, t; }"
        : "=r"(a) : "l"(p));
    return a;
}
__device__ __forceinline__ void cpasync16(uint32_t dst, const float* src) {
    size_t g = __cvta_generic_to_global((const void*)src);
    asm volatile("cp.async.cg.shared.global [%0], [%1], 16;"
                 :: "r"(dst), "l"(g) : "memory");
}
__device__ __forceinline__ void mma8(float* c, uint32_t a0, uint32_t a1,
                                     uint32_t a2, uint32_t a3,
                                     uint32_t b0, uint32_t b1) {
    asm volatile(
        "mma.sync.aligned.m16n8k8.row.col.f32.tf32.tf32.f32 "
        "{%0,%1,%2,%3}, {%4,%5,%6,%7}, {%8,%9}, {%0,%1,%2,%3};"
        : "+f"(c[0]), "+f"(c[1]), "+f"(c[2]), "+f"(c[3])
        : "r"(a0), "r"(a1), "r"(a2), "r"(a3), "r"(b0), "r"(b1));
}

// ---------------------------------------------------------------------------
// Kernel 1: prototypes -> normalized, tf32 split, chunk-major + validity
// ---------------------------------------------------------------------------
__global__ void proto_kernel(const float* __restrict__ sup_x,
                             const float* __restrict__ sup_y) {
    __shared__ float sh[256];
    int p = blockIdx.x;
    int s = p >> 6, ij = p & 63, i = ij >> 3, j = ij & 7;
    int c = threadIdx.x;

    const float* base = sup_x + (((size_t)(s * 256 + c)) * 64 + i * 8) * 64 + j * 8;
    float sum = 0.f;
#pragma unroll
    for (int di = 0; di < 8; di++) {
        const float4* r = (const float4*)(base + di * 64);
        float4 a = r[0], b4 = r[1];
        sum += ((a.x + a.y) + (a.z + a.w)) + ((b4.x + b4.y) + (b4.z + b4.w));
    }
    float f = sum * (1.0f / 64.0f);

    sh[c] = f * f;
    __syncthreads();
    for (int st = 128; st > 0; st >>= 1) {
        if (c < st) sh[c] += sh[c + st];
        __syncthreads();
    }
    float inv = 1.0f / fmaxf(sqrtf(sh[0]), 1e-4f);
    float v = f * inv;
    float vh = to_tf32(v), vl = to_tf32(v - vh);
    int ct = c >> 4, kk = c & 15;
    g_protoH[ct * 4096 + kk * 256 + p] = vh;
    g_protoL[ct * 4096 + kk * 256 + p] = vl;
    __syncthreads();

    float m = 0.f;
    if (c < 64) {
        int di = c >> 3, dj = c & 7;
        float y = sup_y[(size_t)s * 4096 + (i * 8 + di) * 64 + (j * 8 + dj)];
        m = (y > 0.95f) ? 1.f : 0.f;
    }
    sh[c] = m;
    __syncthreads();
    for (int st = 128; st > 0; st >>= 1) {
        if (c < st) sh[c] += sh[c + st];
        __syncthreads();
    }
    if (c == 0) g_valid[p] = (sh[0] * (1.0f / 64.0f) > 0.5f) ? 1 : 0;
}

__global__ void grid_kernel(const float* __restrict__ sup_y, float* __restrict__ out) {
    int idx = blockIdx.x * 256 + threadIdx.x;
    if (idx < 16384)
        out[262144 + idx] = (sup_y[idx] > 0.95f) ? 1.f : 0.f;
}

// ---------------------------------------------------------------------------
// Kernel 3: 3xTF32 mma.sync GEMM + fused masked softmax / argmax / pred
// grid = 32 batches * 64 tiles(64 px) ; 256 threads, 8 warps (4 wm x 2 wn)
// K processed in 16 chunks of 16, A double-buffered via cp.async.
// ---------------------------------------------------------------------------
__global__ void __launch_bounds__(256, 2)
dist_kernel(const float* __restrict__ qry, float* __restrict__ out) {
    extern __shared__ __align__(16) float sm[];
    float* QH = sm + OFF_QH;
    float* QL = sm + OFF_QL;
    float* SQ = sm + OFF_SQ;
    float* QN = sm + OFF_QN;
    uint32_t* VM = (uint32_t*)(sm + OFF_VM);
    float* RA = sm + OFF_RA;
    int*   RI = (int*)(sm + OFF_RI);
    float* RS = sm + OFF_RS;
    float* RW = sm + OFF_RW;

    int tid = threadIdx.x, w = tid >> 5, l = tid & 31;
    int wm = w & 3, wn = w >> 2;

    unsigned bal = __ballot_sync(0xffffffffu, g_valid[tid] != 0);
    if (l == 0) VM[w] = bal;

    int b = blockIdx.x >> 6, n0 = (blockIdx.x & 63) << 6;
    const float* Qbase = qry + (size_t)b * 256 * 4096 + n0;

    float acc[4][4][4];
#pragma unroll
    for (int tm = 0; tm < 4; tm++)
#pragma unroll
        for (int tn = 0; tn < 4; tn++)
#pragma unroll
            for (int e = 0; e < 4; e++) acc[tm][tn][e] = 0.f;

    float4 qv;
    float4 ssq4 = make_float4(0.f, 0.f, 0.f, 0.f);
    const int kk0 = tid >> 4, nf = tid & 15;

    // ---- prologue: chunk 0 A cp.async + Q regs ----
    {
#pragma unroll
        for (int i = 0; i < 8; i++) {
            int seg = tid + i * 256;          // 0..2047
            int mat = seg >> 10;              // 0=H, 1=L
            int row = (seg >> 6) & 15, col = (seg & 63) << 2;
            const float* src = (mat ? g_protoL : g_protoH) + row * 256 + col;
            cpasync16(s2u(sm + OFF_A0 + mat * (16 * AS) + row * AS + col), src);
        }
        asm volatile("cp.async.commit_group;" ::: "memory");
        qv = *(const float4*)(Qbase + (size_t)kk0 * 4096 + nf * 4);
    }

    const int ka = l & 3, ga = l >> 2;

    for (int ct = 0; ct < 16; ct++) {
        int stg = ct & 1;
        float* AH = sm + (stg ? OFF_A1 : OFF_A0);
        float* AL = AH + 16 * AS;
        float* AHn = sm + (stg ? OFF_A0 : OFF_A1);

        if (ct < 15) {
            const float* sH = g_protoH + (ct + 1) * 4096;
            const float* sL = g_protoL + (ct + 1) * 4096;
#pragma unroll
            for (int i = 0; i < 8; i++) {
                int seg = tid + i * 256;
                int mat = seg >> 10;
                int row = (seg >> 6) & 15, col = (seg & 63) << 2;
                const float* src = (mat ? sL : sH) + row * 256 + col;
                cpasync16(s2u(AHn + mat * (16 * AS) + row * AS + col), src);
            }
            asm volatile("cp.async.commit_group;" ::: "memory");
        }

        // split + store current chunk's Q, accumulate ssq
        {
            float4 v = qv, hv, lv;
            hv.x = to_tf32(v.x); lv.x = to_tf32(v.x - hv.x); ssq4.x = fmaf(v.x, v.x, ssq4.x);
            hv.y = to_tf32(v.y); lv.y = to_tf32(v.y - hv.y); ssq4.y = fmaf(v.y, v.y, ssq4.y);
            hv.z = to_tf32(v.z); lv.z = to_tf32(v.z - hv.z); ssq4.z = fmaf(v.z, v.z, ssq4.z);
            hv.w = to_tf32(v.w); lv.w = to_tf32(v.w - hv.w); ssq4.w = fmaf(v.w, v.w, ssq4.w);
            *(float4*)(QH + kk0 * QS + nf * 4) = hv;
            *(float4*)(QL + kk0 * QS + nf * 4) = lv;
        }

        if (ct < 15) asm volatile("cp.async.wait_group 1;" ::: "memory");
        else         asm volatile("cp.async.wait_group 0;" ::: "memory");
        __syncthreads();

        if (ct < 15) {
            qv = *(const float4*)(Qbase + (size_t)((ct + 1) * 16 + kk0) * 4096 + nf * 4);
        }

        // ---- MMA: 2 ksteps of 8 ----
#pragma unroll
        for (int ks = 0; ks < 2; ks++) {
            uint32_t bh[4][2], bl[4][2];
            const int qb = (ks * 8 + ka) * QS + wn * 32 + ga;
#pragma unroll
            for (int tn = 0; tn < 4; tn++) {
                bh[tn][0] = __float_as_uint(QH[qb + tn * 8]);
                bh[tn][1] = __float_as_uint(QH[qb + tn * 8 + 4 * QS]);
                bl[tn][0] = __float_as_uint(QL[qb + tn * 8]);
                bl[tn][1] = __float_as_uint(QL[qb + tn * 8 + 4 * QS]);
            }
            const int ab = (ks * 8 + ka) * AS + wm * 64 + ga;
#pragma unroll
            for (int tm = 0; tm < 4; tm++) {
                int a0i = ab + tm * 16;
                uint32_t ah0 = __float_as_uint(AH[a0i]);
                uint32_t ah1 = __float_as_uint(AH[a0i + 8]);
                uint32_t ah2 = __float_as_uint(AH[a0i + 4 * AS]);
                uint32_t ah3 = __float_as_uint(AH[a0i + 4 * AS + 8]);
                uint32_t al0 = __float_as_uint(AL[a0i]);
                uint32_t al1 = __float_as_uint(AL[a0i + 8]);
                uint32_t al2 = __float_as_uint(AL[a0i + 4 * AS]);
                uint32_t al3 = __float_as_uint(AL[a0i + 4 * AS + 8]);
#pragma unroll
                for (int tn = 0; tn < 4; tn++) {
                    mma8(acc[tm][tn], ah0, ah1, ah2, ah3, bh[tn][0], bh[tn][1]);
                    mma8(acc[tm][tn], ah0, ah1, ah2, ah3, bl[tn][0], bl[tn][1]);
                    mma8(acc[tm][tn], al0, al1, al2, al3, bh[tn][0], bh[tn][1]);
                }
            }
        }
        __syncthreads();
    }

    // ---- qnorm reduction (deterministic) ----
    *(float4*)(SQ + kk0 * 64 + nf * 4) = ssq4;
    __syncthreads();
    if (tid < 64) {
        float s = 0.f;
#pragma unroll
        for (int j = 0; j < 16; j++) s += SQ[j * 64 + tid];
        QN[tid] = 20.0f / fmaxf(sqrtf(s), 1e-4f);
    }

    // ---- write dS transposed [n][p] (reuses tile smem) ----
    float* dS = sm;
    {
        int r0 = wm * 64 + ga;
        int nc0 = wn * 32 + 2 * ka;
#pragma unroll
        for (int tm = 0; tm < 4; tm++) {
            int r = r0 + tm * 16;
#pragma unroll
            for (int tn = 0; tn < 4; tn++) {
                int n = nc0 + tn * 8;
                dS[n * DSS + r]           = acc[tm][tn][0];
                dS[(n + 1) * DSS + r]     = acc[tm][tn][1];
                dS[n * DSS + r + 8]       = acc[tm][tn][2];
                dS[(n + 1) * DSS + r + 8] = acc[tm][tn][3];
            }
        }
    }
    __syncthreads();

    // ---- online masked softmax + argmax over proto quarters ----
    const float NEG = __int_as_float(0xff800000);
    int q = tid >> 6, n = tid & 63;
    float sc = QN[n];
    uint32_t m0 = VM[q * 2], m1 = VM[q * 2 + 1];
    float best = NEG, se = 0.f, ws = 0.f;
    int bidx = q * 64;
    const float4* row = (const float4*)(dS + n * DSS + q * 64);
#pragma unroll 4
    for (int i = 0; i < 16; i++) {
        float4 v = row[i];
        float vv[4] = {v.x, v.y, v.z, v.w};
#pragma unroll
        for (int e = 0; e < 4; e++) {
            int p = i * 4 + e;
            uint32_t ok = ((p < 32 ? m0 : m1) >> (p & 31)) & 1u;
            if (ok) {
                float d = vv[e] * sc;
                if (d > best) {
                    float rr = expf(best - d);
                    se = se * rr + 1.f; ws = ws * rr + d;
                    best = d; bidx = q * 64 + p;
                } else {
                    float e2 = expf(d - best);
                    se += e2; ws = fmaf(e2, d, ws);
                }
            }
        }
    }
    RA[q * 64 + n] = best; RI[q * 64 + n] = bidx;
    RS[q * 64 + n] = se;   RW[q * 64 + n] = ws;
    __syncthreads();

    if (tid < 64) {
        float B = NEG, SE = 0.f, WS = 0.f; int I = 0;
#pragma unroll
        for (int qq = 0; qq < 4; qq++) {
            float bq = RA[qq * 64 + tid];
            float sq = RS[qq * 64 + tid], wq = RW[qq * 64 + tid];
            if (bq > B) {
                float r = (B == NEG) ? 0.f : expf(B - bq);
                SE = SE * r + sq; WS = WS * r + wq;
                B = bq; I = RI[qq * 64 + tid];
            } else {
                float r = (bq == NEG) ? 0.f : expf(bq - B);
                SE += sq * r; WS += wq * r;
            }
        }
        size_t o = (size_t)b * 4096 + n0 + tid;
        out[o] = WS / SE;
        out[131072 + o] = (float)I;
    }
}

extern "C" void kernel_launch(void* const* d_in, const int* in_sizes, int n_in,
                              void* d_out, int out_size) {
    const float* qry   = (const float*)d_in[0];
    const float* sup_x = (const float*)d_in[1];
    const float* sup_y = (const float*)d_in[2];
    float* out = (float*)d_out;

    cudaFuncSetAttribute(dist_kernel,
                         cudaFuncAttributeMaxDynamicSharedMemorySize, SMEM_BYTES);

    proto_kernel<<<256, 256>>>(sup_x, sup_y);
    grid_kernel<<<64, 256>>>(sup_y, out);
    dist_kernel<<<2048, 256, SMEM_BYTES>>>(qry, out);
}

// round 6
// speedup vs baseline: 1.5615x; 1.0350x over previous
#include <cuda_runtime.h>
#include <cstdint>
#include <math.h>

// Pre-split prototypes (tf32 hi/lo), chunk-major contiguous:
// g_protoH[ct*4096 + kk*256 + p] = hi(protoN[p][ct*16+kk]),  ct=0..15, kk=0..15
__device__ __align__(16) float g_protoH[16 * 4096];
__device__ __align__(16) float g_protoL[16 * 4096];
__device__ int g_valid[256];

// ---- smem layout (floats) ----
#define AS   260          // A tile row stride (16 rows x 260), H then L per stage
#define QS   68           // Q tile row stride (16 rows x 68)
#define DSS  268          // dS row stride (64 rows x 268)
#define OFF_A0  0
#define OFF_A1  8320      // 2*16*260
#define OFF_Q   16640     // 2 bufs x (QH 1088 + QL 1088) = 4352
#define QBUF    2176
#define OFF_SQ  20992     // 16 x 64
#define OFF_QN  22016     // 64
#define OFF_VM  22080     // 8 u32
#define OFF_RA  22088
#define OFF_RI  22344
#define OFF_RS  22600
#define OFF_RW  22856
#define SMEM_FLOATS 23112
#define SMEM_BYTES (SMEM_FLOATS * 4)   // 92.4 KB -> 2 CTAs/SM

__device__ __forceinline__ float to_tf32(float x) {
    float r; asm("cvt.rna.tf32.f32 %0, %1;" : "=f"(r) : "f"(x)); return r;
}
__device__ __forceinline__ uint32_t s2u(const void* p) {
    uint32_t a;
    asm("{ .reg .u64 t; cvta.to.shared.u64 t, %1; cvt.u32.u64 %0, t; }"
        : "=r"(a) : "l"(p));
    return a;
}
__device__ __forceinline__ void cpasync16(uint32_t dst, const float* src) {
    size_t g = __cvta_generic_to_global((const void*)src);
    asm volatile("cp.async.cg.shared.global [%0], [%1], 16;"
                 :: "r"(dst), "l"(g) : "memory");
}
__device__ __forceinline__ void mma8(float* c, uint32_t a0, uint32_t a1,
                                     uint32_t a2, uint32_t a3,
                                     uint32_t b0, uint32_t b1) {
    asm volatile(
        "mma.sync.aligned.m16n8k8.row.col.f32.tf32.tf32.f32 "
        "{%0,%1,%2,%3}, {%4,%5,%6,%7}, {%8,%9}, {%0,%1,%2,%3};"
        : "+f"(c[0]), "+f"(c[1]), "+f"(c[2]), "+f"(c[3])
        : "r"(a0), "r"(a1), "r"(a2), "r"(a3), "r"(b0), "r"(b1));
}

// ---------------------------------------------------------------------------
// Kernel 1: prototypes -> normalized, tf32 split, chunk-major + validity
// ---------------------------------------------------------------------------
__global__ void proto_kernel(const float* __restrict__ sup_x,
                             const float* __restrict__ sup_y) {
    __shared__ float sh[256];
    int p = blockIdx.x;
    int s = p >> 6, ij = p & 63, i = ij >> 3, j = ij & 7;
    int c = threadIdx.x;

    const float* base = sup_x + (((size_t)(s * 256 + c)) * 64 + i * 8) * 64 + j * 8;
    float sum = 0.f;
#pragma unroll
    for (int di = 0; di < 8; di++) {
        const float4* r = (const float4*)(base + di * 64);
        float4 a = r[0], b4 = r[1];
        sum += ((a.x + a.y) + (a.z + a.w)) + ((b4.x + b4.y) + (b4.z + b4.w));
    }
    float f = sum * (1.0f / 64.0f);

    sh[c] = f * f;
    __syncthreads();
    for (int st = 128; st > 0; st >>= 1) {
        if (c < st) sh[c] += sh[c + st];
        __syncthreads();
    }
    float inv = 1.0f / fmaxf(sqrtf(sh[0]), 1e-4f);
    float v = f * inv;
    float vh = to_tf32(v), vl = to_tf32(v - vh);
    int ct = c >> 4, kk = c & 15;
    g_protoH[ct * 4096 + kk * 256 + p] = vh;
    g_protoL[ct * 4096 + kk * 256 + p] = vl;
    __syncthreads();

    float m = 0.f;
    if (c < 64) {
        int di = c >> 3, dj = c & 7;
        float y = sup_y[(size_t)s * 4096 + (i * 8 + di) * 64 + (j * 8 + dj)];
        m = (y > 0.95f) ? 1.f : 0.f;
    }
    sh[c] = m;
    __syncthreads();
    for (int st = 128; st > 0; st >>= 1) {
        if (c < st) sh[c] += sh[c + st];
        __syncthreads();
    }
    if (c == 0) g_valid[p] = (sh[0] * (1.0f / 64.0f) > 0.5f) ? 1 : 0;
}

__global__ void grid_kernel(const float* __restrict__ sup_y, float* __restrict__ out) {
    int idx = blockIdx.x * 256 + threadIdx.x;
    if (idx < 16384)
        out[262144 + idx] = (sup_y[idx] > 0.95f) ? 1.f : 0.f;
}

// ---------------------------------------------------------------------------
// Kernel 3: 3xTF32 mma.sync GEMM + fused masked softmax / argmax / pred
// grid = 32 batches * 64 tiles(64 px) ; 256 threads, 8 warps (4 wm x 2 wn)
// K in 16 chunks of 16; A and Q both double-buffered; ONE barrier per chunk.
// ---------------------------------------------------------------------------
__global__ void __launch_bounds__(256, 2)
dist_kernel(const float* __restrict__ qry, float* __restrict__ out) {
    extern __shared__ __align__(16) float sm[];
    float* SQ = sm + OFF_SQ;
    float* QN = sm + OFF_QN;
    uint32_t* VM = (uint32_t*)(sm + OFF_VM);
    float* RA = sm + OFF_RA;
    int*   RI = (int*)(sm + OFF_RI);
    float* RS = sm + OFF_RS;
    float* RW = sm + OFF_RW;

    int tid = threadIdx.x, w = tid >> 5, l = tid & 31;
    int wm = w & 3, wn = w >> 2;

    unsigned bal = __ballot_sync(0xffffffffu, g_valid[tid] != 0);
    if (l == 0) VM[w] = bal;

    int b = blockIdx.x >> 6, n0 = (blockIdx.x & 63) << 6;
    const float* Qbase = qry + (size_t)b * 256 * 4096 + n0;

    float acc[4][4][4];
#pragma unroll
    for (int tm = 0; tm < 4; tm++)
#pragma unroll
        for (int tn = 0; tn < 4; tn++)
#pragma unroll
            for (int e = 0; e < 4; e++) acc[tm][tn][e] = 0.f;

    float4 qv;
    float4 ssq4 = make_float4(0.f, 0.f, 0.f, 0.f);
    const int kk0 = tid >> 4, nf = tid & 15;
    const int ka = l & 3, ga = l >> 2;

    // ---- prologue: A(0) cp.async ; Q(0) split+STS ; qv <- chunk 1 ----
    {
#pragma unroll
        for (int i = 0; i < 8; i++) {
            int seg = tid + i * 256;
            int mat = seg >> 10;
            int row = (seg >> 6) & 15, col = (seg & 63) << 2;
            const float* src = (mat ? g_protoL : g_protoH) + row * 256 + col;
            cpasync16(s2u(sm + OFF_A0 + mat * (16 * AS) + row * AS + col), src);
        }
        asm volatile("cp.async.commit_group;" ::: "memory");

        qv = *(const float4*)(Qbase + (size_t)kk0 * 4096 + nf * 4);
        float4 v = qv, hv, lv;
        hv.x = to_tf32(v.x); lv.x = to_tf32(v.x - hv.x); ssq4.x = fmaf(v.x, v.x, ssq4.x);
        hv.y = to_tf32(v.y); lv.y = to_tf32(v.y - hv.y); ssq4.y = fmaf(v.y, v.y, ssq4.y);
        hv.z = to_tf32(v.z); lv.z = to_tf32(v.z - hv.z); ssq4.z = fmaf(v.z, v.z, ssq4.z);
        hv.w = to_tf32(v.w); lv.w = to_tf32(v.w - hv.w); ssq4.w = fmaf(v.w, v.w, ssq4.w);
        *(float4*)(sm + OFF_Q + kk0 * QS + nf * 4) = hv;
        *(float4*)(sm + OFF_Q + 1088 + kk0 * QS + nf * 4) = lv;

        qv = *(const float4*)(Qbase + (size_t)(16 + kk0) * 4096 + nf * 4);
    }

    for (int ct = 0; ct < 16; ct++) {
        int stg = ct & 1;
        float* AH = sm + (stg ? OFF_A1 : OFF_A0);
        float* AL = AH + 16 * AS;
        float* QH = sm + OFF_Q + stg * QBUF;
        float* QL = QH + 1088;

        asm volatile("cp.async.wait_group 0;" ::: "memory");
        __syncthreads();

        if (ct < 15) {
            // issue A(ct+1) into the stage consumed at chunk ct-1
            float* AHn = sm + (stg ? OFF_A0 : OFF_A1);
            const float* sH = g_protoH + (ct + 1) * 4096;
            const float* sL = g_protoL + (ct + 1) * 4096;
#pragma unroll
            for (int i = 0; i < 8; i++) {
                int seg = tid + i * 256;
                int mat = seg >> 10;
                int row = (seg >> 6) & 15, col = (seg & 63) << 2;
                const float* src = (mat ? sL : sH) + row * 256 + col;
                cpasync16(s2u(AHn + mat * (16 * AS) + row * AS + col), src);
            }
            asm volatile("cp.async.commit_group;" ::: "memory");

            // split + STS Q(ct+1) into the other Q buffer (overlaps MMAs below)
            float* QHd = sm + OFF_Q + (stg ^ 1) * QBUF;
            float* QLd = QHd + 1088;
            float4 v = qv, hv, lv;
            hv.x = to_tf32(v.x); lv.x = to_tf32(v.x - hv.x); ssq4.x = fmaf(v.x, v.x, ssq4.x);
            hv.y = to_tf32(v.y); lv.y = to_tf32(v.y - hv.y); ssq4.y = fmaf(v.y, v.y, ssq4.y);
            hv.z = to_tf32(v.z); lv.z = to_tf32(v.z - hv.z); ssq4.z = fmaf(v.z, v.z, ssq4.z);
            hv.w = to_tf32(v.w); lv.w = to_tf32(v.w - hv.w); ssq4.w = fmaf(v.w, v.w, ssq4.w);
            *(float4*)(QHd + kk0 * QS + nf * 4) = hv;
            *(float4*)(QLd + kk0 * QS + nf * 4) = lv;

            if (ct < 14)
                qv = *(const float4*)(Qbase + (size_t)((ct + 2) * 16 + kk0) * 4096 + nf * 4);
        }

        // ---- MMA: 2 ksteps of 8 ----
#pragma unroll
        for (int ks = 0; ks < 2; ks++) {
            uint32_t bh[4][2], bl[4][2];
            const int qb = (ks * 8 + ka) * QS + wn * 32 + ga;
#pragma unroll
            for (int tn = 0; tn < 4; tn++) {
                bh[tn][0] = __float_as_uint(QH[qb + tn * 8]);
                bh[tn][1] = __float_as_uint(QH[qb + tn * 8 + 4 * QS]);
                bl[tn][0] = __float_as_uint(QL[qb + tn * 8]);
                bl[tn][1] = __float_as_uint(QL[qb + tn * 8 + 4 * QS]);
            }
            const int ab = (ks * 8 + ka) * AS + wm * 64 + ga;
#pragma unroll
            for (int tm = 0; tm < 4; tm++) {
                int a0i = ab + tm * 16;
                uint32_t ah0 = __float_as_uint(AH[a0i]);
                uint32_t ah1 = __float_as_uint(AH[a0i + 8]);
                uint32_t ah2 = __float_as_uint(AH[a0i + 4 * AS]);
                uint32_t ah3 = __float_as_uint(AH[a0i + 4 * AS + 8]);
                uint32_t al0 = __float_as_uint(AL[a0i]);
                uint32_t al1 = __float_as_uint(AL[a0i + 8]);
                uint32_t al2 = __float_as_uint(AL[a0i + 4 * AS]);
                uint32_t al3 = __float_as_uint(AL[a0i + 4 * AS + 8]);
#pragma unroll
                for (int tn = 0; tn < 4; tn++) {
                    mma8(acc[tm][tn], ah0, ah1, ah2, ah3, bh[tn][0], bh[tn][1]);
                    mma8(acc[tm][tn], ah0, ah1, ah2, ah3, bl[tn][0], bl[tn][1]);
                    mma8(acc[tm][tn], al0, al1, al2, al3, bh[tn][0], bh[tn][1]);
                }
            }
        }
    }

    // ---- qnorm reduction (deterministic) ----
    *(float4*)(SQ + kk0 * 64 + nf * 4) = ssq4;
    __syncthreads();
    if (tid < 64) {
        float s = 0.f;
#pragma unroll
        for (int j = 0; j < 16; j++) s += SQ[j * 64 + tid];
        QN[tid] = 20.0f / fmaxf(sqrtf(s), 1e-4f);
    }

    // ---- write dS transposed [n][p] (reuses tile smem) ----
    float* dS = sm;
    {
        int r0 = wm * 64 + ga;
        int nc0 = wn * 32 + 2 * ka;
#pragma unroll
        for (int tm = 0; tm < 4; tm++) {
            int r = r0 + tm * 16;
#pragma unroll
            for (int tn = 0; tn < 4; tn++) {
                int n = nc0 + tn * 8;
                dS[n * DSS + r]           = acc[tm][tn][0];
                dS[(n + 1) * DSS + r]     = acc[tm][tn][1];
                dS[n * DSS + r + 8]       = acc[tm][tn][2];
                dS[(n + 1) * DSS + r + 8] = acc[tm][tn][3];
            }
        }
    }
    __syncthreads();

    // ---- online masked softmax + argmax over proto quarters ----
    const float NEG = __int_as_float(0xff800000);
    int q = tid >> 6, n = tid & 63;
    float sc = QN[n];
    uint32_t m0 = VM[q * 2], m1 = VM[q * 2 + 1];
    float best = NEG, se = 0.f, ws = 0.f;
    int bidx = q * 64;
    const float4* row = (const float4*)(dS + n * DSS + q * 64);
#pragma unroll 4
    for (int i = 0; i < 16; i++) {
        float4 v = row[i];
        float vv[4] = {v.x, v.y, v.z, v.w};
#pragma unroll
        for (int e = 0; e < 4; e++) {
            int p = i * 4 + e;
            uint32_t ok = ((p < 32 ? m0 : m1) >> (p & 31)) & 1u;
            if (ok) {
                float d = vv[e] * sc;
                if (d > best) {
                    float rr = __expf(best - d);
                    se = se * rr + 1.f; ws = ws * rr + d;
                    best = d; bidx = q * 64 + p;
                } else {
                    float e2 = __expf(d - best);
                    se += e2; ws = fmaf(e2, d, ws);
                }
            }
        }
    }
    RA[q * 64 + n] = best; RI[q * 64 + n] = bidx;
    RS[q * 64 + n] = se;   RW[q * 64 + n] = ws;
    __syncthreads();

    if (tid < 64) {
        float B = NEG, SE = 0.f, WS = 0.f; int I = 0;
#pragma unroll
        for (int qq = 0; qq < 4; qq++) {
            float bq = RA[qq * 64 + tid];
            float sq = RS[qq * 64 + tid], wq = RW[qq * 64 + tid];
            if (bq > B) {
                float r = (B == NEG) ? 0.f : __expf(B - bq);
                SE = SE * r + sq; WS = WS * r + wq;
                B = bq; I = RI[qq * 64 + tid];
            } else {
                float r = (bq == NEG) ? 0.f : __expf(bq - B);
                SE += sq * r; WS += wq * r;
            }
        }
        size_t o = (size_t)b * 4096 + n0 + tid;
        out[o] = WS / SE;
        out[131072 + o] = (float)I;
    }
}

extern "C" void kernel_launch(void* const* d_in, const int* in_sizes, int n_in,
                              void* d_out, int out_size) {
    const float* qry   = (const float*)d_in[0];
    const float* sup_x = (const float*)d_in[1];
    const float* sup_y = (const float*)d_in[2];
    float* out = (float*)d_out;

    cudaFuncSetAttribute(dist_kernel,
                         cudaFuncAttributeMaxDynamicSharedMemorySize, SMEM_BYTES);

    proto_kernel<<<256, 256>>>(sup_x, sup_y);
    grid_kernel<<<64, 256>>>(sup_y, out);
    dist_kernel<<<2048, 256, SMEM_BYTES>>>(qry, out);
}

// round 8
// speedup vs baseline: 2.8037x; 1.7955x over previous
#include <cuda_runtime.h>
#include <cuda_fp16.h>
#include <cstdint>
#include <math.h>

// Pre-split prototypes (fp16 hi/lo), half2 k-pair packed, chunk-major:
// element (ct, kp, p) = half2{ hi/lo(proto[p][ct*32+2kp]), hi/lo(...+2kp+1) }
// stored as uint32: g_protoH2[ct*4096 + kp*256 + p]
__device__ __align__(16) unsigned g_protoH2[8 * 4096];
__device__ __align__(16) unsigned g_protoL2[8 * 4096];
__device__ int g_valid[256];

// ---- smem layout (4B units) ----
#define AS   260          // A tile row stride (16 kp rows x 260), H then L per stage
#define QS   68           // Q tile row stride (16 kp rows x 68)
#define DSS  268          // dS row stride (64 rows x 268)
#define OFF_A0  0
#define OFF_A1  8320      // 2*16*260
#define OFF_Q   16640     // 2 bufs x (QH 1088 + QL 1088) = 4352
#define QBUF    2176
#define OFF_SQ  20992     // 16 x 64
#define OFF_QN  22016     // 64
#define OFF_VM  22080     // 8 u32
#define OFF_RA  22088
#define OFF_RI  22344
#define OFF_RS  22600
#define OFF_RW  22856
#define SMEM_FLOATS 23112
#define SMEM_BYTES (SMEM_FLOATS * 4)   // 92.4 KB -> 2 CTAs/SM

__device__ __forceinline__ uint32_t s2u(const void* p) {
    uint32_t a;
    asm("{ .reg .u64 t; cvta.to.shared.u64 t, %1; cvt.u32.u64 %0, t; }"
        : "=r"(a) : "l"(p));
    return a;
}
__device__ __forceinline__ void cpasync16(uint32_t dst, const void* src) {
    size_t g = __cvta_generic_to_global(src);
    asm volatile("cp.async.cg.shared.global [%0], [%1], 16;"
                 :: "r"(dst), "l"(g) : "memory");
}
// pack two fp16 (from floats, rn) into a uint32: lo half = a (even k), hi = b (odd k)
__device__ __forceinline__ uint32_t pack_h2(float a, float b) {
    __half_raw ra = (__half_raw)__float2half_rn(a);
    __half_raw rb = (__half_raw)__float2half_rn(b);
    return (uint32_t)ra.x | ((uint32_t)rb.x << 16);
}
__device__ __forceinline__ float h2f(float x) {   // fp16 round-trip value
    return __half2float(__float2half_rn(x));
}
// fp16 m16n8k16, fp32 accumulate
__device__ __forceinline__ void mma16(float* c, uint32_t a0, uint32_t a1,
                                      uint32_t a2, uint32_t a3,
                                      uint32_t b0, uint32_t b1) {
    asm volatile(
        "mma.sync.aligned.m16n8k16.row.col.f32.f16.f16.f32 "
        "{%0,%1,%2,%3}, {%4,%5,%6,%7}, {%8,%9}, {%0,%1,%2,%3};"
        : "+f"(c[0]), "+f"(c[1]), "+f"(c[2]), "+f"(c[3])
        : "r"(a0), "r"(a1), "r"(a2), "r"(a3), "r"(b0), "r"(b1));
}

// ---------------------------------------------------------------------------
// Kernel 1: prototypes -> normalized, fp16 hi/lo split, pair-packed + validity
// ---------------------------------------------------------------------------
__global__ void proto_kernel(const float* __restrict__ sup_x,
                             const float* __restrict__ sup_y) {
    __shared__ float sh[256];
    __shared__ float vv_sm[256];
    int p = blockIdx.x;
    int s = p >> 6, ij = p & 63, i = ij >> 3, j = ij & 7;
    int c = threadIdx.x;

    const float* base = sup_x + (((size_t)(s * 256 + c)) * 64 + i * 8) * 64 + j * 8;
    float sum = 0.f;
#pragma unroll
    for (int di = 0; di < 8; di++) {
        const float4* r = (const float4*)(base + di * 64);
        float4 a = r[0], b4 = r[1];
        sum += ((a.x + a.y) + (a.z + a.w)) + ((b4.x + b4.y) + (b4.z + b4.w));
    }
    float f = sum * (1.0f / 64.0f);

    sh[c] = f * f;
    __syncthreads();
    for (int st = 128; st > 0; st >>= 1) {
        if (c < st) sh[c] += sh[c + st];
        __syncthreads();
    }
    float inv = 1.0f / fmaxf(sqrtf(sh[0]), 1e-4f);
    float v = f * inv;
    vv_sm[c] = v;
    __syncthreads();

    // threads 0..127 each pack one k-pair (kp) for this proto
    if (c < 128) {
        int ct = c >> 4, kp = c & 15;
        float v0 = vv_sm[ct * 32 + 2 * kp];
        float v1 = vv_sm[ct * 32 + 2 * kp + 1];
        g_protoH2[ct * 4096 + kp * 256 + p] = pack_h2(v0, v1);
        g_protoL2[ct * 4096 + kp * 256 + p] =
            pack_h2(v0 - h2f(v0), v1 - h2f(v1));
    }
    __syncthreads();

    float m = 0.f;
    if (c < 64) {
        int di = c >> 3, dj = c & 7;
        float y = sup_y[(size_t)s * 4096 + (i * 8 + di) * 64 + (j * 8 + dj)];
        m = (y > 0.95f) ? 1.f : 0.f;
    }
    sh[c] = m;
    __syncthreads();
    for (int st = 128; st > 0; st >>= 1) {
        if (c < st) sh[c] += sh[c + st];
        __syncthreads();
    }
    if (c == 0) g_valid[p] = (sh[0] * (1.0f / 64.0f) > 0.5f) ? 1 : 0;
}

__global__ void grid_kernel(const float* __restrict__ sup_y, float* __restrict__ out) {
    int idx = blockIdx.x * 256 + threadIdx.x;
    if (idx < 16384)
        out[262144 + idx] = (sup_y[idx] > 0.95f) ? 1.f : 0.f;
}

// ---------------------------------------------------------------------------
// Kernel 3: 3x fp16-split mma.sync(k16) GEMM + fused softmax / argmax / pred
// grid = 32 batches * 64 tiles(64 px) ; 256 threads, 8 warps (4 wm x 2 wn)
// K in 8 chunks of 32; A and Q double-buffered; ONE barrier per chunk.
// ---------------------------------------------------------------------------
__global__ void __launch_bounds__(256, 2)
dist_kernel(const float* __restrict__ qry, float* __restrict__ out) {
    extern __shared__ __align__(16) float sm[];
    float* SQ = sm + OFF_SQ;
    float* QN = sm + OFF_QN;
    uint32_t* VM = (uint32_t*)(sm + OFF_VM);
    float* RA = sm + OFF_RA;
    int*   RI = (int*)(sm + OFF_RI);
    float* RS = sm + OFF_RS;
    float* RW = sm + OFF_RW;

    int tid = threadIdx.x, w = tid >> 5, l = tid & 31;
    int wm = w & 3, wn = w >> 2;

    unsigned bal = __ballot_sync(0xffffffffu, g_valid[tid] != 0);
    if (l == 0) VM[w] = bal;

    int b = blockIdx.x >> 6, n0 = (blockIdx.x & 63) << 6;
    const float* Qbase = qry + (size_t)b * 256 * 4096 + n0;

    float acc[4][4][4];
#pragma unroll
    for (int tm = 0; tm < 4; tm++)
#pragma unroll
        for (int tn = 0; tn < 4; tn++)
#pragma unroll
            for (int e = 0; e < 4; e++) acc[tm][tn][e] = 0.f;

    float4 qv0, qv1;                    // even-k row, odd-k row
    float4 ssq4 = make_float4(0.f, 0.f, 0.f, 0.f);
    const int kp0 = tid >> 4, nf = tid & 15;
    const int ka = l & 3, ga = l >> 2;

#define SPLIT_STORE(QHdst, QLdst)                                              \
    {                                                                          \
        float x0[4] = {qv0.x, qv0.y, qv0.z, qv0.w};                            \
        float x1[4] = {qv1.x, qv1.y, qv1.z, qv1.w};                            \
        uint32_t hq[4], lq[4];                                                 \
        _Pragma("unroll")                                                      \
        for (int e = 0; e < 4; e++) {                                          \
            hq[e] = pack_h2(x0[e], x1[e]);                                     \
            lq[e] = pack_h2(x0[e] - h2f(x0[e]), x1[e] - h2f(x1[e]));           \
        }                                                                      \
        ssq4.x = fmaf(x0[0], x0[0], fmaf(x1[0], x1[0], ssq4.x));               \
        ssq4.y = fmaf(x0[1], x0[1], fmaf(x1[1], x1[1], ssq4.y));               \
        ssq4.z = fmaf(x0[2], x0[2], fmaf(x1[2], x1[2], ssq4.z));               \
        ssq4.w = fmaf(x0[3], x0[3], fmaf(x1[3], x1[3], ssq4.w));               \
        *(uint4*)((QHdst) + kp0 * QS + nf * 4) = make_uint4(hq[0], hq[1], hq[2], hq[3]); \
        *(uint4*)((QLdst) + kp0 * QS + nf * 4) = make_uint4(lq[0], lq[1], lq[2], lq[3]); \
    }

    // ---- prologue: A(0) cp.async ; Q(0) split+STS ; prefetch Q(1) ----
    {
#pragma unroll
        for (int i = 0; i < 8; i++) {
            int seg = tid + i * 256;
            int mat = seg >> 10;
            int row = (seg >> 6) & 15, col = (seg & 63) << 2;
            const unsigned* src = (mat ? g_protoL2 : g_protoH2) + row * 256 + col;
            cpasync16(s2u(sm + OFF_A0 + mat * (16 * AS) + row * AS + col), src);
        }
        asm volatile("cp.async.commit_group;" ::: "memory");

        qv0 = *(const float4*)(Qbase + (size_t)(2 * kp0) * 4096 + nf * 4);
        qv1 = *(const float4*)(Qbase + (size_t)(2 * kp0 + 1) * 4096 + nf * 4);
        float* QHd = sm + OFF_Q;
        float* QLd = QHd + 1088;
        SPLIT_STORE(QHd, QLd)

        qv0 = *(const float4*)(Qbase + (size_t)(32 + 2 * kp0) * 4096 + nf * 4);
        qv1 = *(const float4*)(Qbase + (size_t)(32 + 2 * kp0 + 1) * 4096 + nf * 4);
    }

    for (int ct = 0; ct < 8; ct++) {
        int stg = ct & 1;
        float* AH = sm + (stg ? OFF_A1 : OFF_A0);
        float* AL = AH + 16 * AS;
        float* QH = sm + OFF_Q + stg * QBUF;
        float* QL = QH + 1088;

        asm volatile("cp.async.wait_group 0;" ::: "memory");
        __syncthreads();

        if (ct < 7) {
            float* AHn = sm + (stg ? OFF_A0 : OFF_A1);
            const unsigned* sH = g_protoH2 + (ct + 1) * 4096;
            const unsigned* sL = g_protoL2 + (ct + 1) * 4096;
#pragma unroll
            for (int i = 0; i < 8; i++) {
                int seg = tid + i * 256;
                int mat = seg >> 10;
                int row = (seg >> 6) & 15, col = (seg & 63) << 2;
                const unsigned* src = (mat ? sL : sH) + row * 256 + col;
                cpasync16(s2u(AHn + mat * (16 * AS) + row * AS + col), src);
            }
            asm volatile("cp.async.commit_group;" ::: "memory");

            float* QHd = sm + OFF_Q + (stg ^ 1) * QBUF;
            float* QLd = QHd + 1088;
            SPLIT_STORE(QHd, QLd)

            if (ct < 6) {
                const float* qc = Qbase + (size_t)((ct + 2) * 32) * 4096;
                qv0 = *(const float4*)(qc + (size_t)(2 * kp0) * 4096 + nf * 4);
                qv1 = *(const float4*)(qc + (size_t)(2 * kp0 + 1) * 4096 + nf * 4);
            }
        }

        // ---- MMA: 2 ksteps of k16 ----
#pragma unroll
        for (int ks = 0; ks < 2; ks++) {
            uint32_t bh[4][2], bl[4][2];
            const int qb = (ks * 8 + ka) * QS + wn * 32 + ga;
#pragma unroll
            for (int tn = 0; tn < 4; tn++) {
                bh[tn][0] = __float_as_uint(QH[qb + tn * 8]);
                bh[tn][1] = __float_as_uint(QH[qb + tn * 8 + 4 * QS]);
                bl[tn][0] = __float_as_uint(QL[qb + tn * 8]);
                bl[tn][1] = __float_as_uint(QL[qb + tn * 8 + 4 * QS]);
            }
            const int ab = (ks * 8 + ka) * AS + wm * 64 + ga;
#pragma unroll
            for (int tm = 0; tm < 4; tm++) {
                int a0i = ab + tm * 16;
                uint32_t ah0 = __float_as_uint(AH[a0i]);
                uint32_t ah1 = __float_as_uint(AH[a0i + 8]);
                uint32_t ah2 = __float_as_uint(AH[a0i + 4 * AS]);
                uint32_t ah3 = __float_as_uint(AH[a0i + 4 * AS + 8]);
                uint32_t al0 = __float_as_uint(AL[a0i]);
                uint32_t al1 = __float_as_uint(AL[a0i + 8]);
                uint32_t al2 = __float_as_uint(AL[a0i + 4 * AS]);
                uint32_t al3 = __float_as_uint(AL[a0i + 4 * AS + 8]);
#pragma unroll
                for (int tn = 0; tn < 4; tn++) {
                    mma16(acc[tm][tn], ah0, ah1, ah2, ah3, bh[tn][0], bh[tn][1]);
                    mma16(acc[tm][tn], ah0, ah1, ah2, ah3, bl[tn][0], bl[tn][1]);
                    mma16(acc[tm][tn], al0, al1, al2, al3, bh[tn][0], bh[tn][1]);
                }
            }
        }
    }

    // ---- qnorm reduction (deterministic) ----
    *(float4*)(SQ + kp0 * 64 + nf * 4) = ssq4;
    __syncthreads();
    if (tid < 64) {
        float s = 0.f;
#pragma unroll
        for (int j = 0; j < 16; j++) s += SQ[j * 64 + tid];
        QN[tid] = 20.0f / fmaxf(sqrtf(s), 1e-4f);
    }

    // ---- write dS transposed [n][p] (reuses tile smem) ----
    float* dS = sm;
    {
        int r0 = wm * 64 + ga;
        int nc0 = wn * 32 + 2 * ka;
#pragma unroll
        for (int tm = 0; tm < 4; tm++) {
            int r = r0 + tm * 16;
#pragma unroll
            for (int tn = 0; tn < 4; tn++) {
                int n = nc0 + tn * 8;
                dS[n * DSS + r]           = acc[tm][tn][0];
                dS[(n + 1) * DSS + r]     = acc[tm][tn][1];
                dS[n * DSS + r + 8]       = acc[tm][tn][2];
                dS[(n + 1) * DSS + r + 8] = acc[tm][tn][3];
            }
        }
    }
    __syncthreads();

    // ---- online masked softmax + argmax over proto quarters ----
    const float NEG = __int_as_float(0xff800000);
    int q = tid >> 6, n = tid & 63;
    float sc = QN[n];
    uint32_t m0 = VM[q * 2], m1 = VM[q * 2 + 1];
    float best = NEG, se = 0.f, ws = 0.f;
    int bidx = q * 64;
    const float4* row = (const float4*)(dS + n * DSS + q * 64);
#pragma unroll 4
    for (int i = 0; i < 16; i++) {
        float4 v = row[i];
        float vv[4] = {v.x, v.y, v.z, v.w};
#pragma unroll
        for (int e = 0; e < 4; e++) {
            int p = i * 4 + e;
            uint32_t ok = ((p < 32 ? m0 : m1) >> (p & 31)) & 1u;
            if (ok) {
                float d = vv[e] * sc;
                if (d > best) {
                    float rr = __expf(best - d);
                    se = se * rr + 1.f; ws = ws * rr + d;
                    best = d; bidx = q * 64 + p;
                } else {
                    float e2 = __expf(d - best);
                    se += e2; ws = fmaf(e2, d, ws);
                }
            }
        }
    }
    RA[q * 64 + n] = best; RI[q * 64 + n] = bidx;
    RS[q * 64 + n] = se;   RW[q * 64 + n] = ws;
    __syncthreads();

    if (tid < 64) {
        float B = NEG, SE = 0.f, WS = 0.f; int I = 0;
#pragma unroll
        for (int qq = 0; qq < 4; qq++) {
            float bq = RA[qq * 64 + tid];
            float sq = RS[qq * 64 + tid], wq = RW[qq * 64 + tid];
            if (bq > B) {
                float r = (B == NEG) ? 0.f : __expf(B - bq);
                SE = SE * r + sq; WS = WS * r + wq;
                B = bq; I = RI[qq * 64 + tid];
            } else {
                float r = (bq == NEG) ? 0.f : __expf(bq - B);
                SE += sq * r; WS += wq * r;
            }
        }
        size_t o = (size_t)b * 4096 + n0 + tid;
        out[o] = WS / SE;
        out[131072 + o] = (float)I;
    }
}

extern "C" void kernel_launch(void* const* d_in, const int* in_sizes, int n_in,
                              void* d_out, int out_size) {
    const float* qry   = (const float*)d_in[0];
    const float* sup_x = (const float*)d_in[1];
    const float* sup_y = (const float*)d_in[2];
    float* out = (float*)d_out;

    cudaFuncSetAttribute(dist_kernel,
                         cudaFuncAttributeMaxDynamicSharedMemorySize, SMEM_BYTES);

    proto_kernel<<<256, 256>>>(sup_x, sup_y);
    grid_kernel<<<64, 256>>>(sup_y, out);
    dist_kernel<<<2048, 256, SMEM_BYTES>>>(qry, out);
}

// round 9
// speedup vs baseline: 3.4973x; 1.2474x over previous
#include <cuda_runtime.h>
#include <cuda_fp16.h>
#include <cstdint>
#include <math.h>

// fp32 normalized protos (staging), validity, compacted split images + LUT
__device__ __align__(16) float g_protoF[256 * 256];
__device__ int g_valid[256];
__device__ __align__(16) unsigned g_protoH2[8 * 4096];  // compacted: [ct][kp][cidx]
__device__ __align__(16) unsigned g_protoL2[8 * 4096];
__device__ int g_map[256];
__device__ int g_vcnt;

// ---- smem layout (4B units) ----
#define AS   260          // A tile row stride (16 kp rows x 260), H then L per stage
#define QS   68           // Q tile row stride (16 kp rows x 68)
#define DSS  269          // dS row stride (64 pixel rows x 269 proto cols)
#define OFF_A0  0
#define OFF_A1  8320      // 2*16*260
#define OFF_Q   16640     // 2 bufs x (QH 1088 + QL 1088) = 4352
#define QBUF    2176
#define OFF_SQ  20992     // 16 x 64
#define OFF_QN  22016     // 64
#define OFF_MP  22080     // 256 ints (compact -> orig map)
#define OFF_RA  22336
#define OFF_RI  22592
#define OFF_RS  22848
#define OFF_RW  23104
#define SMEM_FLOATS 23360
#define SMEM_BYTES (SMEM_FLOATS * 4)   // 93.4 KB -> 2 CTAs/SM

__device__ __forceinline__ uint32_t s2u(const void* p) {
    uint32_t a;
    asm("{ .reg .u64 t; cvta.to.shared.u64 t, %1; cvt.u32.u64 %0, t; }"
        : "=r"(a) : "l"(p));
    return a;
}
__device__ __forceinline__ void cpasync16(uint32_t dst, const void* src) {
    size_t g = __cvta_generic_to_global(src);
    asm volatile("cp.async.cg.shared.global [%0], [%1], 16;"
                 :: "r"(dst), "l"(g) : "memory");
}
__device__ __forceinline__ uint32_t pack_h2(float a, float b) {
    __half_raw ra = (__half_raw)__float2half_rn(a);
    __half_raw rb = (__half_raw)__float2half_rn(b);
    return (uint32_t)ra.x | ((uint32_t)rb.x << 16);
}
__device__ __forceinline__ float h2f(float x) {
    return __half2float(__float2half_rn(x));
}
__device__ __forceinline__ void mma16(float* c, uint32_t a0, uint32_t a1,
                                      uint32_t a2, uint32_t a3,
                                      uint32_t b0, uint32_t b1) {
    asm volatile(
        "mma.sync.aligned.m16n8k16.row.col.f32.f16.f16.f32 "
        "{%0,%1,%2,%3}, {%4,%5,%6,%7}, {%8,%9}, {%0,%1,%2,%3};"
        : "+f"(c[0]), "+f"(c[1]), "+f"(c[2]), "+f"(c[3])
        : "r"(a0), "r"(a1), "r"(a2), "r"(a3), "r"(b0), "r"(b1));
}

// ---------------------------------------------------------------------------
// Kernel 1: prototypes -> normalized fp32 staging + validity
// ---------------------------------------------------------------------------
__global__ void proto_kernel(const float* __restrict__ sup_x,
                             const float* __restrict__ sup_y) {
    __shared__ float sh[256];
    int p = blockIdx.x;
    int s = p >> 6, ij = p & 63, i = ij >> 3, j = ij & 7;
    int c = threadIdx.x;

    const float* base = sup_x + (((size_t)(s * 256 + c)) * 64 + i * 8) * 64 + j * 8;
    float sum = 0.f;
#pragma unroll
    for (int di = 0; di < 8; di++) {
        const float4* r = (const float4*)(base + di * 64);
        float4 a = r[0], b4 = r[1];
        sum += ((a.x + a.y) + (a.z + a.w)) + ((b4.x + b4.y) + (b4.z + b4.w));
    }
    float f = sum * (1.0f / 64.0f);

    sh[c] = f * f;
    __syncthreads();
    for (int st = 128; st > 0; st >>= 1) {
        if (c < st) sh[c] += sh[c + st];
        __syncthreads();
    }
    float inv = 1.0f / fmaxf(sqrtf(sh[0]), 1e-4f);
    g_protoF[p * 256 + c] = f * inv;
    __syncthreads();

    float m = 0.f;
    if (c < 64) {
        int di = c >> 3, dj = c & 7;
        float y = sup_y[(size_t)s * 4096 + (i * 8 + di) * 64 + (j * 8 + dj)];
        m = (y > 0.95f) ? 1.f : 0.f;
    }
    sh[c] = m;
    __syncthreads();
    for (int st = 128; st > 0; st >>= 1) {
        if (c < st) sh[c] += sh[c + st];
        __syncthreads();
    }
    if (c == 0) g_valid[p] = (sh[0] * (1.0f / 64.0f) > 0.5f) ? 1 : 0;
}

// ---------------------------------------------------------------------------
// Kernel 2: compaction — prefix sum valid protos, build LUT, write compacted
// fp16 hi/lo split half2 chunk images. Single block, 256 threads.
// ---------------------------------------------------------------------------
__global__ void compact_kernel(const float* __restrict__ sup_y,
                               float* __restrict__ out) {
    __shared__ int sc[256];
    int p = threadIdx.x;
    int v = g_valid[p];
    sc[p] = v;
    __syncthreads();
    // Hillis-Steele inclusive scan
    for (int off = 1; off < 256; off <<= 1) {
        int add = (p >= off) ? sc[p - off] : 0;
        __syncthreads();
        sc[p] += add;
        __syncthreads();
    }
    int pos = sc[p];               // inclusive
    if (p == 255) g_vcnt = pos;
    if (v) {
        int ci = pos - 1;
        g_map[ci] = p;
        const float* src = g_protoF + p * 256;
#pragma unroll 4
        for (int kidx = 0; kidx < 128; kidx++) {
            int ct = kidx >> 4, kp = kidx & 15;
            float v0 = src[ct * 32 + 2 * kp];
            float v1 = src[ct * 32 + 2 * kp + 1];
            g_protoH2[ct * 4096 + kp * 256 + ci] = pack_h2(v0, v1);
            g_protoL2[ct * 4096 + kp * 256 + ci] =
                pack_h2(v0 - h2f(v0), v1 - h2f(v1));
        }
    }
    // proto_grid passthrough folded in (each thread does 64 pixels)
    for (int idx = p; idx < 16384; idx += 256)
        out[262144 + idx] = (sup_y[idx] > 0.95f) ? 1.f : 0.f;
}

// ---------------------------------------------------------------------------
// Kernel 3: 3x fp16-split mma.sync(k16) GEMM over COMPACTED protos
//           + fused softmax / argmax / pred
// grid = 32 batches * 64 tiles(64 px) ; 256 threads, 8 warps (4 wm x 2 wn)
// proto m-tile t (16 protos) -> warp wm = t&3, local tm = t>>2 (balanced).
// ---------------------------------------------------------------------------
__global__ void __launch_bounds__(256, 2)
dist_kernel(const float* __restrict__ qry, float* __restrict__ out) {
    extern __shared__ __align__(16) float sm[];
    float* SQ = sm + OFF_SQ;
    float* QN = sm + OFF_QN;
    int*   MP = (int*)(sm + OFF_MP);
    float* RA = sm + OFF_RA;
    int*   RI = (int*)(sm + OFF_RI);
    float* RS = sm + OFF_RS;
    float* RW = sm + OFF_RW;

    int tid = threadIdx.x, w = tid >> 5, l = tid & 31;
    int wm = w & 3, wn = w >> 2;

    const int V = g_vcnt;
    const int nTiles = (V + 15) >> 4;
    const int V16 = nTiles << 4;
    const int tmax = (nTiles + 3 - wm) >> 2;   // tiles for this warp
    MP[tid] = g_map[tid];

    int b = blockIdx.x >> 6, n0 = (blockIdx.x & 63) << 6;
    const float* Qbase = qry + (size_t)b * 256 * 4096 + n0;

    float acc[4][4][4];
#pragma unroll
    for (int tm = 0; tm < 4; tm++)
#pragma unroll
        for (int tn = 0; tn < 4; tn++)
#pragma unroll
            for (int e = 0; e < 4; e++) acc[tm][tn][e] = 0.f;

    float4 qv0, qv1;
    float4 ssq4 = make_float4(0.f, 0.f, 0.f, 0.f);
    const int kp0 = tid >> 4, nf = tid & 15;
    const int ka = l & 3, ga = l >> 2;

#define SPLIT_STORE(QHdst, QLdst)                                              \
    {                                                                          \
        float x0[4] = {qv0.x, qv0.y, qv0.z, qv0.w};                            \
        float x1[4] = {qv1.x, qv1.y, qv1.z, qv1.w};                            \
        uint32_t hq[4], lq[4];                                                 \
        _Pragma("unroll")                                                      \
        for (int e = 0; e < 4; e++) {                                          \
            hq[e] = pack_h2(x0[e], x1[e]);                                     \
            lq[e] = pack_h2(x0[e] - h2f(x0[e]), x1[e] - h2f(x1[e]));           \
        }                                                                      \
        ssq4.x = fmaf(x0[0], x0[0], fmaf(x1[0], x1[0], ssq4.x));               \
        ssq4.y = fmaf(x0[1], x0[1], fmaf(x1[1], x1[1], ssq4.y));               \
        ssq4.z = fmaf(x0[2], x0[2], fmaf(x1[2], x1[2], ssq4.z));               \
        ssq4.w = fmaf(x0[3], x0[3], fmaf(x1[3], x1[3], ssq4.w));               \
        *(uint4*)((QHdst) + kp0 * QS + nf * 4) = make_uint4(hq[0], hq[1], hq[2], hq[3]); \
        *(uint4*)((QLdst) + kp0 * QS + nf * 4) = make_uint4(lq[0], lq[1], lq[2], lq[3]); \
    }

#define A_LOAD(dstbase, srcH, srcL)                                            \
    _Pragma("unroll")                                                          \
    for (int i = 0; i < 8; i++) {                                              \
        int seg = tid + i * 256;                                               \
        int mat = seg >> 10;                                                   \
        int row = (seg >> 6) & 15, col = (seg & 63) << 2;                      \
        if (col < V16) {                                                       \
            const unsigned* src = (mat ? (srcL) : (srcH)) + row * 256 + col;   \
            cpasync16(s2u((dstbase) + mat * (16 * AS) + row * AS + col), src); \
        }                                                                      \
    }

    // ---- prologue: A(0) cp.async ; Q(0) split+STS ; prefetch Q(1) ----
    {
        A_LOAD(sm + OFF_A0, g_protoH2, g_protoL2)
        asm volatile("cp.async.commit_group;" ::: "memory");

        qv0 = *(const float4*)(Qbase + (size_t)(2 * kp0) * 4096 + nf * 4);
        qv1 = *(const float4*)(Qbase + (size_t)(2 * kp0 + 1) * 4096 + nf * 4);
        float* QHd = sm + OFF_Q;
        float* QLd = QHd + 1088;
        SPLIT_STORE(QHd, QLd)

        qv0 = *(const float4*)(Qbase + (size_t)(32 + 2 * kp0) * 4096 + nf * 4);
        qv1 = *(const float4*)(Qbase + (size_t)(32 + 2 * kp0 + 1) * 4096 + nf * 4);
    }

    for (int ct = 0; ct < 8; ct++) {
        int stg = ct & 1;
        float* AH = sm + (stg ? OFF_A1 : OFF_A0);
        float* AL = AH + 16 * AS;
        float* QH = sm + OFF_Q + stg * QBUF;
        float* QL = QH + 1088;

        asm volatile("cp.async.wait_group 0;" ::: "memory");
        __syncthreads();

        if (ct < 7) {
            float* AHn = sm + (stg ? OFF_A0 : OFF_A1);
            const unsigned* sH = g_protoH2 + (ct + 1) * 4096;
            const unsigned* sL = g_protoL2 + (ct + 1) * 4096;
            A_LOAD(AHn, sH, sL)
            asm volatile("cp.async.commit_group;" ::: "memory");

            float* QHd = sm + OFF_Q + (stg ^ 1) * QBUF;
            float* QLd = QHd + 1088;
            SPLIT_STORE(QHd, QLd)

            if (ct < 6) {
                const float* qc = Qbase + (size_t)((ct + 2) * 32) * 4096;
                qv0 = *(const float4*)(qc + (size_t)(2 * kp0) * 4096 + nf * 4);
                qv1 = *(const float4*)(qc + (size_t)(2 * kp0 + 1) * 4096 + nf * 4);
            }
        }

        // ---- MMA: 2 ksteps of k16, only active proto tiles ----
#pragma unroll
        for (int ks = 0; ks < 2; ks++) {
            uint32_t bh[4][2], bl[4][2];
            const int qb = (ks * 8 + ka) * QS + wn * 32 + ga;
#pragma unroll
            for (int tn = 0; tn < 4; tn++) {
                bh[tn][0] = __float_as_uint(QH[qb + tn * 8]);
                bh[tn][1] = __float_as_uint(QH[qb + tn * 8 + 4 * QS]);
                bl[tn][0] = __float_as_uint(QL[qb + tn * 8]);
                bl[tn][1] = __float_as_uint(QL[qb + tn * 8 + 4 * QS]);
            }
            const int ab = (ks * 8 + ka) * AS + wm * 16 + ga;
#pragma unroll
            for (int tm = 0; tm < 4; tm++) {
                if (tm < tmax) {
                    int a0i = ab + tm * 64;
                    uint32_t ah0 = __float_as_uint(AH[a0i]);
                    uint32_t ah1 = __float_as_uint(AH[a0i + 8]);
                    uint32_t ah2 = __float_as_uint(AH[a0i + 4 * AS]);
                    uint32_t ah3 = __float_as_uint(AH[a0i + 4 * AS + 8]);
                    uint32_t al0 = __float_as_uint(AL[a0i]);
                    uint32_t al1 = __float_as_uint(AL[a0i + 8]);
                    uint32_t al2 = __float_as_uint(AL[a0i + 4 * AS]);
                    uint32_t al3 = __float_as_uint(AL[a0i + 4 * AS + 8]);
#pragma unroll
                    for (int tn = 0; tn < 4; tn++) {
                        mma16(acc[tm][tn], ah0, ah1, ah2, ah3, bh[tn][0], bh[tn][1]);
                        mma16(acc[tm][tn], ah0, ah1, ah2, ah3, bl[tn][0], bl[tn][1]);
                        mma16(acc[tm][tn], al0, al1, al2, al3, bh[tn][0], bh[tn][1]);
                    }
                }
            }
        }
    }

    // ---- qnorm reduction (deterministic) ----
    *(float4*)(SQ + kp0 * 64 + nf * 4) = ssq4;
    __syncthreads();
    if (tid < 64) {
        float s = 0.f;
#pragma unroll
        for (int j = 0; j < 16; j++) s += SQ[j * 64 + tid];
        QN[tid] = 20.0f / fmaxf(sqrtf(s), 1e-4f);
    }

    // ---- write dS transposed [pixel n][compact proto c] ----
    float* dS = sm;
    {
        int nc0 = wn * 32 + 2 * ka;
#pragma unroll
        for (int tm = 0; tm < 4; tm++) {
            if (tm < tmax) {
                int r = tm * 64 + wm * 16 + ga;
#pragma unroll
                for (int tn = 0; tn < 4; tn++) {
                    int n = nc0 + tn * 8;
                    dS[n * DSS + r]           = acc[tm][tn][0];
                    dS[(n + 1) * DSS + r]     = acc[tm][tn][1];
                    dS[n * DSS + r + 8]       = acc[tm][tn][2];
                    dS[(n + 1) * DSS + r + 8] = acc[tm][tn][3];
                }
            }
        }
    }
    __syncthreads();

    // ---- online softmax + argmax over compacted protos (all valid) ----
    const float NEG = __int_as_float(0xff800000);
    int q = tid >> 6, n = tid & 63;
    float sc = QN[n];
    int L = (V + 3) >> 2;
    int c0 = q * L, c1 = min(c0 + L, V);
    float best = NEG, se = 0.f, ws = 0.f;
    int bidx = 0;
    for (int c = c0; c < c1; c++) {
        float d = dS[n * DSS + c] * sc;
        if (d > best) {
            float rr = __expf(best - d);
            se = se * rr + 1.f; ws = ws * rr + d;
            best = d; bidx = MP[c];
        } else {
            float e2 = __expf(d - best);
            se += e2; ws = fmaf(e2, d, ws);
        }
    }
    RA[q * 64 + n] = best; RI[q * 64 + n] = bidx;
    RS[q * 64 + n] = se;   RW[q * 64 + n] = ws;
    __syncthreads();

    if (tid < 64) {
        float B = NEG, SE = 0.f, WS = 0.f; int I = 0;
#pragma unroll
        for (int qq = 0; qq < 4; qq++) {
            float bq = RA[qq * 64 + tid];
            float sq = RS[qq * 64 + tid], wq = RW[qq * 64 + tid];
            if (bq > B) {
                float r = (B == NEG) ? 0.f : __expf(B - bq);
                SE = SE * r + sq; WS = WS * r + wq;
                B = bq; I = RI[qq * 64 + tid];
            } else {
                float r = (bq == NEG) ? 0.f : __expf(bq - B);
                SE += sq * r; WS += wq * r;
            }
        }
        size_t o = (size_t)b * 4096 + n0 + tid;
        out[o] = WS / SE;
        out[131072 + o] = (float)I;
    }
}

extern "C" void kernel_launch(void* const* d_in, const int* in_sizes, int n_in,
                              void* d_out, int out_size) {
    const float* qry   = (const float*)d_in[0];
    const float* sup_x = (const float*)d_in[1];
    const float* sup_y = (const float*)d_in[2];
    float* out = (float*)d_out;

    cudaFuncSetAttribute(dist_kernel,
                         cudaFuncAttributeMaxDynamicSharedMemorySize, SMEM_BYTES);

    proto_kernel<<<256, 256>>>(sup_x, sup_y);
    compact_kernel<<<1, 256>>>(sup_y, out);
    dist_kernel<<<2048, 256, SMEM_BYTES>>>(qry, out);
}

// round 10
// speedup vs baseline: 3.9754x; 1.1367x over previous
#include <cuda_runtime.h>
#include <cuda_fp16.h>
#include <cstdint>
#include <math.h>

// fp32 normalized protos (staging), validity, compacted split images + LUT
__device__ __align__(16) float g_protoF[256 * 256];
__device__ int g_valid[256];
__device__ __align__(16) unsigned g_protoH2[8 * 4096];  // compacted: [ct][kp][cidx]
__device__ __align__(16) unsigned g_protoL2[8 * 4096];
__device__ int g_map[256];
__device__ int g_vcnt;

// ---- smem layout (4B units) ----
#define AS   260          // A tile row stride (16 kp rows x 260)
#define QS2  132          // Q tile row stride (16 kp rows x 132 px-u32)
#define DSS  269          // dS row stride (64 pixel rows x 269 proto cols)
#define OFF_A0  0
#define OFF_A1  8320      // 2*16*260
#define OFF_Q   16640     // 2 bufs x (QH 2112 + QL 2112)
#define QBUF    4224
#define SMEM_FLOATS 25088
#define SMEM_BYTES (SMEM_FLOATS * 4)   // 100.4 KB -> 2 CTAs/SM
// post-mainloop aliases (inside the same region)
#define OFF_SQ  17216     // 16 x 128
#define OFF_QN  19264     // 128
#define OFF_RA  19392
#define OFF_RI  19648
#define OFF_RS  19904
#define OFF_RW  20160

__device__ __forceinline__ uint32_t s2u(const void* p) {
    uint32_t a;
    asm("{ .reg .u64 t; cvta.to.shared.u64 t, %1; cvt.u32.u64 %0, t; }"
        : "=r"(a) : "l"(p));
    return a;
}
__device__ __forceinline__ void cpasync16(uint32_t dst, const void* src) {
    size_t g = __cvta_generic_to_global(src);
    asm volatile("cp.async.cg.shared.global [%0], [%1], 16;"
                 :: "r"(dst), "l"(g) : "memory");
}
__device__ __forceinline__ uint32_t pack_h2(float a, float b) {
    __half_raw ra = (__half_raw)__float2half_rn(a);
    __half_raw rb = (__half_raw)__float2half_rn(b);
    return (uint32_t)ra.x | ((uint32_t)rb.x << 16);
}
__device__ __forceinline__ float h2f(float x) {
    return __half2float(__float2half_rn(x));
}
__device__ __forceinline__ void mma16(float* c, uint32_t a0, uint32_t a1,
                                      uint32_t a2, uint32_t a3,
                                      uint32_t b0, uint32_t b1) {
    asm volatile(
        "mma.sync.aligned.m16n8k16.row.col.f32.f16.f16.f32 "
        "{%0,%1,%2,%3}, {%4,%5,%6,%7}, {%8,%9}, {%0,%1,%2,%3};"
        : "+f"(c[0]), "+f"(c[1]), "+f"(c[2]), "+f"(c[3])
        : "r"(a0), "r"(a1), "r"(a2), "r"(a3), "r"(b0), "r"(b1));
}

// ---------------------------------------------------------------------------
// Kernel 1: prototypes -> normalized fp32 staging + validity
// ---------------------------------------------------------------------------
__global__ void proto_kernel(const float* __restrict__ sup_x,
                             const float* __restrict__ sup_y) {
    __shared__ float sh[256];
    int p = blockIdx.x;
    int s = p >> 6, ij = p & 63, i = ij >> 3, j = ij & 7;
    int c = threadIdx.x;

    const float* base = sup_x + (((size_t)(s * 256 + c)) * 64 + i * 8) * 64 + j * 8;
    float sum = 0.f;
#pragma unroll
    for (int di = 0; di < 8; di++) {
        const float4* r = (const float4*)(base + di * 64);
        float4 a = r[0], b4 = r[1];
        sum += ((a.x + a.y) + (a.z + a.w)) + ((b4.x + b4.y) + (b4.z + b4.w));
    }
    float f = sum * (1.0f / 64.0f);

    sh[c] = f * f;
    __syncthreads();
    for (int st = 128; st > 0; st >>= 1) {
        if (c < st) sh[c] += sh[c + st];
        __syncthreads();
    }
    float inv = 1.0f / fmaxf(sqrtf(sh[0]), 1e-4f);
    g_protoF[p * 256 + c] = f * inv;
    __syncthreads();

    float m = 0.f;
    if (c < 64) {
        int di = c >> 3, dj = c & 7;
        float y = sup_y[(size_t)s * 4096 + (i * 8 + di) * 64 + (j * 8 + dj)];
        m = (y > 0.95f) ? 1.f : 0.f;
    }
    sh[c] = m;
    __syncthreads();
    for (int st = 128; st > 0; st >>= 1) {
        if (c < st) sh[c] += sh[c + st];
        __syncthreads();
    }
    if (c == 0) g_valid[p] = (sh[0] * (1.0f / 64.0f) > 0.5f) ? 1 : 0;
}

// ---------------------------------------------------------------------------
// Kernel 2: compaction + proto_grid passthrough (1 block, 256 threads)
// ---------------------------------------------------------------------------
__global__ void compact_kernel(const float* __restrict__ sup_y,
                               float* __restrict__ out) {
    __shared__ int sc[256];
    int p = threadIdx.x;
    int v = g_valid[p];
    sc[p] = v;
    __syncthreads();
    for (int off = 1; off < 256; off <<= 1) {
        int add = (p >= off) ? sc[p - off] : 0;
        __syncthreads();
        sc[p] += add;
        __syncthreads();
    }
    int pos = sc[p];
    if (p == 255) g_vcnt = pos;
    if (v) {
        int ci = pos - 1;
        g_map[ci] = p;
        const float* src = g_protoF + p * 256;
#pragma unroll 4
        for (int kidx = 0; kidx < 128; kidx++) {
            int ct = kidx >> 4, kp = kidx & 15;
            float v0 = src[ct * 32 + 2 * kp];
            float v1 = src[ct * 32 + 2 * kp + 1];
            g_protoH2[ct * 4096 + kp * 256 + ci] = pack_h2(v0, v1);
            g_protoL2[ct * 4096 + kp * 256 + ci] =
                pack_h2(v0 - h2f(v0), v1 - h2f(v1));
        }
    }
    for (int idx = p; idx < 16384; idx += 256)
        out[262144 + idx] = (sup_y[idx] > 0.95f) ? 1.f : 0.f;
}

// ---------------------------------------------------------------------------
// Kernel 3: 3x fp16-split mma.sync(k16) over COMPACTED protos, 128-px tiles
// grid = 32 batches * 32 tiles(128 px) ; 256 threads, 8 warps (2 wm x 4 wn)
// proto m-tile t -> warp wm = t&1, tm = t>>1 (supports nTiles <= 8).
// ---------------------------------------------------------------------------
__global__ void __launch_bounds__(256, 2)
dist_kernel(const float* __restrict__ qry, float* __restrict__ out) {
    extern __shared__ __align__(16) float sm[];
    float* SQ = sm + OFF_SQ;
    float* QN = sm + OFF_QN;
    float* RA = sm + OFF_RA;
    int*   RI = (int*)(sm + OFF_RI);
    float* RS = sm + OFF_RS;
    float* RW = sm + OFF_RW;

    int tid = threadIdx.x, w = tid >> 5, l = tid & 31;
    int wm = w & 1, wn = w >> 1;

    const int V = g_vcnt;
    const int nTiles = (V + 15) >> 4;
    const int V16 = nTiles << 4;
    int tmax = (nTiles + 1 - wm) >> 1;
    if (tmax > 4) tmax = 4;

    int b = blockIdx.x >> 5, n0 = (blockIdx.x & 31) << 7;
    const float* Qbase = qry + (size_t)b * 256 * 4096 + n0;

    float acc[4][4][4];
#pragma unroll
    for (int tm = 0; tm < 4; tm++)
#pragma unroll
        for (int tn = 0; tn < 4; tn++)
#pragma unroll
            for (int e = 0; e < 4; e++) acc[tm][tn][e] = 0.f;

    float4 qe0, qe1, qo0, qo1;          // even row (2x float4), odd row
    float ssq8[8];
#pragma unroll
    for (int e = 0; e < 8; e++) ssq8[e] = 0.f;
    const int kp0 = tid >> 4, nf = tid & 15;
    const int ka = l & 3, ga = l >> 2;

#define Q_LOAD(ctv)                                                            \
    {                                                                          \
        const float* qc = Qbase + (size_t)((ctv) * 32 + 2 * kp0) * 4096 + nf * 8; \
        qe0 = *(const float4*)(qc);                                            \
        qe1 = *(const float4*)(qc + 4);                                        \
        qo0 = *(const float4*)(qc + 4096);                                     \
        qo1 = *(const float4*)(qc + 4100);                                     \
    }

#define SPLIT_STORE(QHdst, QLdst)                                              \
    {                                                                          \
        float ev[8] = {qe0.x, qe0.y, qe0.z, qe0.w, qe1.x, qe1.y, qe1.z, qe1.w};\
        float od[8] = {qo0.x, qo0.y, qo0.z, qo0.w, qo1.x, qo1.y, qo1.z, qo1.w};\
        uint32_t hq[8], lq[8];                                                 \
        _Pragma("unroll")                                                      \
        for (int e = 0; e < 8; e++) {                                          \
            hq[e] = pack_h2(ev[e], od[e]);                                     \
            lq[e] = pack_h2(ev[e] - h2f(ev[e]), od[e] - h2f(od[e]));           \
            ssq8[e] = fmaf(ev[e], ev[e], fmaf(od[e], od[e], ssq8[e]));         \
        }                                                                      \
        float* hb = (QHdst) + kp0 * QS2 + nf * 8;                              \
        float* lb = (QLdst) + kp0 * QS2 + nf * 8;                              \
        *(uint4*)hb       = make_uint4(hq[0], hq[1], hq[2], hq[3]);            \
        *(uint4*)(hb + 4) = make_uint4(hq[4], hq[5], hq[6], hq[7]);            \
        *(uint4*)lb       = make_uint4(lq[0], lq[1], lq[2], lq[3]);            \
        *(uint4*)(lb + 4) = make_uint4(lq[4], lq[5], lq[6], lq[7]);            \
    }

#define A_LOAD(dstbase, srcH, srcL)                                            \
    _Pragma("unroll")                                                          \
    for (int i = 0; i < 8; i++) {                                              \
        int seg = tid + i * 256;                                               \
        int mat = seg >> 10;                                                   \
        int row = (seg >> 6) & 15, col = (seg & 63) << 2;                      \
        if (col < V16) {                                                       \
            const unsigned* src = (mat ? (srcL) : (srcH)) + row * 256 + col;   \
            cpasync16(s2u((dstbase) + mat * (16 * AS) + row * AS + col), src); \
        }                                                                      \
    }

    // ---- prologue ----
    {
        A_LOAD(sm + OFF_A0, g_protoH2, g_protoL2)
        asm volatile("cp.async.commit_group;" ::: "memory");
        Q_LOAD(0)
        float* QHd = sm + OFF_Q;
        SPLIT_STORE(QHd, QHd + 2112)
        Q_LOAD(1)
    }

    for (int ct = 0; ct < 8; ct++) {
        int stg = ct & 1;
        float* AH = sm + (stg ? OFF_A1 : OFF_A0);
        float* AL = AH + 16 * AS;
        float* QH = sm + OFF_Q + stg * QBUF;
        float* QL = QH + 2112;

        asm volatile("cp.async.wait_group 0;" ::: "memory");
        __syncthreads();

        if (ct < 7) {
            float* AHn = sm + (stg ? OFF_A0 : OFF_A1);
            const unsigned* sH = g_protoH2 + (ct + 1) * 4096;
            const unsigned* sL = g_protoL2 + (ct + 1) * 4096;
            A_LOAD(AHn, sH, sL)
            asm volatile("cp.async.commit_group;" ::: "memory");

            float* QHd = sm + OFF_Q + (stg ^ 1) * QBUF;
            SPLIT_STORE(QHd, QHd + 2112)
            if (ct < 6) Q_LOAD(ct + 2)
        }

        // ---- MMA: 2 ksteps of k16 ----
#pragma unroll
        for (int ks = 0; ks < 2; ks++) {
            uint32_t bh[4][2], bl[4][2];
            const int qb = (ks * 8 + ka) * QS2 + wn * 32 + ga;
#pragma unroll
            for (int tn = 0; tn < 4; tn++) {
                bh[tn][0] = __float_as_uint(QH[qb + tn * 8]);
                bh[tn][1] = __float_as_uint(QH[qb + tn * 8 + 4 * QS2]);
                bl[tn][0] = __float_as_uint(QL[qb + tn * 8]);
                bl[tn][1] = __float_as_uint(QL[qb + tn * 8 + 4 * QS2]);
            }
            const int ab = (ks * 8 + ka) * AS + wm * 16 + ga;
#pragma unroll
            for (int tm = 0; tm < 4; tm++) {
                if (tm < tmax) {
                    int a0i = ab + tm * 32;
                    uint32_t ah0 = __float_as_uint(AH[a0i]);
                    uint32_t ah1 = __float_as_uint(AH[a0i + 8]);
                    uint32_t ah2 = __float_as_uint(AH[a0i + 4 * AS]);
                    uint32_t ah3 = __float_as_uint(AH[a0i + 4 * AS + 8]);
                    uint32_t al0 = __float_as_uint(AL[a0i]);
                    uint32_t al1 = __float_as_uint(AL[a0i + 8]);
                    uint32_t al2 = __float_as_uint(AL[a0i + 4 * AS]);
                    uint32_t al3 = __float_as_uint(AL[a0i + 4 * AS + 8]);
#pragma unroll
                    for (int tn = 0; tn < 4; tn++) {
                        mma16(acc[tm][tn], ah0, ah1, ah2, ah3, bh[tn][0], bh[tn][1]);
                        mma16(acc[tm][tn], ah0, ah1, ah2, ah3, bl[tn][0], bl[tn][1]);
                        mma16(acc[tm][tn], al0, al1, al2, al3, bh[tn][0], bh[tn][1]);
                    }
                }
            }
        }
    }

    __syncthreads();

    // ---- qnorm reduction (deterministic): SQ[kp0][px] ----
    {
        float* sq = SQ + kp0 * 128 + nf * 8;
        *(float4*)sq       = make_float4(ssq8[0], ssq8[1], ssq8[2], ssq8[3]);
        *(float4*)(sq + 4) = make_float4(ssq8[4], ssq8[5], ssq8[6], ssq8[7]);
    }
    __syncthreads();
    if (tid < 128) {
        float s = 0.f;
#pragma unroll
        for (int j = 0; j < 16; j++) s += SQ[j * 128 + tid];
        QN[tid] = 20.0f / fmaxf(sqrtf(s), 1e-4f);
    }
    __syncthreads();

    // ---- two-phase epilogue over 64-px halves ----
    float* dS = sm;
    const float NEG = __int_as_float(0xff800000);
    const int L = (V + 3) >> 2;

    for (int ph = 0; ph < 2; ph++) {
        if ((wn >> 1) == ph) {
            int nbase = (wn & 1) * 32 + 2 * ka;
#pragma unroll
            for (int tm = 0; tm < 4; tm++) {
                if (tm < tmax) {
                    int r = (tm * 2 + wm) * 16 + ga;
#pragma unroll
                    for (int tn = 0; tn < 4; tn++) {
                        int n = nbase + tn * 8;
                        dS[n * DSS + r]           = acc[tm][tn][0];
                        dS[(n + 1) * DSS + r]     = acc[tm][tn][1];
                        dS[n * DSS + r + 8]       = acc[tm][tn][2];
                        dS[(n + 1) * DSS + r + 8] = acc[tm][tn][3];
                    }
                }
            }
        }
        __syncthreads();

        int q = tid >> 6, n = tid & 63;
        float scl = QN[ph * 64 + n];
        int c0 = q * L, c1 = min(c0 + L, V);
        float best = NEG, se = 0.f, ws = 0.f;
        int bidx = 0;
        for (int c = c0; c < c1; c++) {
            float d = dS[n * DSS + c] * scl;
            if (d > best) {
                float rr = __expf(best - d);
                se = se * rr + 1.f; ws = ws * rr + d;
                best = d; bidx = __ldg(&g_map[c]);
            } else {
                float e2 = __expf(d - best);
                se += e2; ws = fmaf(e2, d, ws);
            }
        }
        RA[q * 64 + n] = best; RI[q * 64 + n] = bidx;
        RS[q * 64 + n] = se;   RW[q * 64 + n] = ws;
        __syncthreads();

        if (tid < 64) {
            float B = NEG, SE = 0.f, WS = 0.f; int I = 0;
#pragma unroll
            for (int qq = 0; qq < 4; qq++) {
                float bq = RA[qq * 64 + tid];
                float sq = RS[qq * 64 + tid], wq = RW[qq * 64 + tid];
                if (bq > B) {
                    float r = (B == NEG) ? 0.f : __expf(B - bq);
                    SE = SE * r + sq; WS = WS * r + wq;
                    B = bq; I = RI[qq * 64 + tid];
                } else {
                    float r = (bq == NEG) ? 0.f : __expf(bq - B);
                    SE += sq * r; WS += wq * r;
                }
            }
            size_t o = (size_t)b * 4096 + n0 + ph * 64 + tid;
            out[o] = WS / SE;
            out[131072 + o] = (float)I;
        }
        __syncthreads();
    }
}

extern "C" void kernel_launch(void* const* d_in, const int* in_sizes, int n_in,
                              void* d_out, int out_size) {
    const float* qry   = (const float*)d_in[0];
    const float* sup_x = (const float*)d_in[1];
    const float* sup_y = (const float*)d_in[2];
    float* out = (float*)d_out;

    cudaFuncSetAttribute(dist_kernel,
                         cudaFuncAttributeMaxDynamicSharedMemorySize, SMEM_BYTES);

    proto_kernel<<<256, 256>>>(sup_x, sup_y);
    compact_kernel<<<1, 256>>>(sup_y, out);
    dist_kernel<<<1024, 256, SMEM_BYTES>>>(qry, out);
}

// round 11
// speedup vs baseline: 4.7969x; 1.2066x over previous
#include <cuda_runtime.h>
#include <cuda_fp16.h>
#include <cstdint>
#include <math.h>

// fp32 normalized protos (staging), validity, compacted split images + LUT
__device__ __align__(16) float g_protoF[256 * 256];
__device__ int g_valid[256];
__device__ int g_ci[256];
__device__ __align__(16) unsigned g_protoH2[8 * 4096];  // compacted: [ct][kp][cidx]
__device__ __align__(16) unsigned g_protoL2[8 * 4096];
__device__ int g_map[256];
__device__ int g_vcnt;

// ---- smem layout (4B units) ----
#define AS   260          // A tile row stride (16 kp rows x 260)
#define QS2  132          // Q tile row stride (16 kp rows x 132 px-u32)
#define DSS  269          // dS row stride (64 pixel rows x 269 proto cols)
#define OFF_A0  0
#define OFF_A1  8320      // 2*16*260
#define OFF_Q   16640     // 2 bufs x (QH 2112 + QL 2112)
#define QBUF    4224
#define SMEM_FLOATS 25088
#define SMEM_BYTES (SMEM_FLOATS * 4)   // 100.4 KB -> 2 CTAs/SM
// post-mainloop aliases (inside the same region)
#define OFF_SQ  17216     // 16 x 128
#define OFF_QN  19264     // 128
#define OFF_RA  19392
#define OFF_RI  19648
#define OFF_RS  19904
#define OFF_RW  20160

__device__ __forceinline__ uint32_t s2u(const void* p) {
    uint32_t a;
    asm("{ .reg .u64 t; cvta.to.shared.u64 t, %1; cvt.u32.u64 %0, t; }"
        : "=r"(a) : "l"(p));
    return a;
}
__device__ __forceinline__ void cpasync16(uint32_t dst, const void* src) {
    size_t g = __cvta_generic_to_global(src);
    asm volatile("cp.async.cg.shared.global [%0], [%1], 16;"
                 :: "r"(dst), "l"(g) : "memory");
}
__device__ __forceinline__ uint32_t pack_h2(float a, float b) {
    __half_raw ra = (__half_raw)__float2half_rn(a);
    __half_raw rb = (__half_raw)__float2half_rn(b);
    return (uint32_t)ra.x | ((uint32_t)rb.x << 16);
}
__device__ __forceinline__ float h2f(float x) {
    return __half2float(__float2half_rn(x));
}
__device__ __forceinline__ void mma16(float* c, uint32_t a0, uint32_t a1,
                                      uint32_t a2, uint32_t a3,
                                      uint32_t b0, uint32_t b1) {
    asm volatile(
        "mma.sync.aligned.m16n8k16.row.col.f32.f16.f16.f32 "
        "{%0,%1,%2,%3}, {%4,%5,%6,%7}, {%8,%9}, {%0,%1,%2,%3};"
        : "+f"(c[0]), "+f"(c[1]), "+f"(c[2]), "+f"(c[3])
        : "r"(a0), "r"(a1), "r"(a2), "r"(a3), "r"(b0), "r"(b1));
}

// ---------------------------------------------------------------------------
// Kernel 1: prototypes -> normalized fp32 staging + validity
// ---------------------------------------------------------------------------
__global__ void proto_kernel(const float* __restrict__ sup_x,
                             const float* __restrict__ sup_y) {
    __shared__ float sh[256];
    int p = blockIdx.x;
    int s = p >> 6, ij = p & 63, i = ij >> 3, j = ij & 7;
    int c = threadIdx.x;

    const float* base = sup_x + (((size_t)(s * 256 + c)) * 64 + i * 8) * 64 + j * 8;
    float sum = 0.f;
#pragma unroll
    for (int di = 0; di < 8; di++) {
        const float4* r = (const float4*)(base + di * 64);
        float4 a = r[0], b4 = r[1];
        sum += ((a.x + a.y) + (a.z + a.w)) + ((b4.x + b4.y) + (b4.z + b4.w));
    }
    float f = sum * (1.0f / 64.0f);

    sh[c] = f * f;
    __syncthreads();
    for (int st = 128; st > 0; st >>= 1) {
        if (c < st) sh[c] += sh[c + st];
        __syncthreads();
    }
    float inv = 1.0f / fmaxf(sqrtf(sh[0]), 1e-4f);
    g_protoF[p * 256 + c] = f * inv;
    __syncthreads();

    float m = 0.f;
    if (c < 64) {
        int di = c >> 3, dj = c & 7;
        float y = sup_y[(size_t)s * 4096 + (i * 8 + di) * 64 + (j * 8 + dj)];
        m = (y > 0.95f) ? 1.f : 0.f;
    }
    sh[c] = m;
    __syncthreads();
    for (int st = 128; st > 0; st >>= 1) {
        if (c < st) sh[c] += sh[c + st];
        __syncthreads();
    }
    if (c == 0) g_valid[p] = (sh[0] * (1.0f / 64.0f) > 0.5f) ? 1 : 0;
}

// ---------------------------------------------------------------------------
// Kernel 2a: scan (1 block) — prefix sum, map, count
// ---------------------------------------------------------------------------
__global__ void scan_kernel() {
    __shared__ int sc[256];
    int p = threadIdx.x;
    int v = g_valid[p];
    sc[p] = v;
    __syncthreads();
    for (int off = 1; off < 256; off <<= 1) {
        int add = (p >= off) ? sc[p - off] : 0;
        __syncthreads();
        sc[p] += add;
        __syncthreads();
    }
    int pos = sc[p];
    if (p == 255) g_vcnt = pos;
    g_ci[p] = pos - 1;
    if (v) g_map[pos - 1] = p;
}

// ---------------------------------------------------------------------------
// Kernel 2b: parallel pack (256 blocks x 128 thr) + proto_grid passthrough
// ---------------------------------------------------------------------------
__global__ void pack_kernel(const float* __restrict__ sup_y,
                            float* __restrict__ out) {
    int p = blockIdx.x, t = threadIdx.x;
    if (t < 64) {
        int idx = p * 64 + t;
        out[262144 + idx] = (sup_y[idx] > 0.95f) ? 1.f : 0.f;
    }
    if (g_valid[p]) {
        int ci = g_ci[p];
        int ct = t >> 4, kp = t & 15;
        const float* src = g_protoF + p * 256;
        float v0 = src[ct * 32 + 2 * kp];
        float v1 = src[ct * 32 + 2 * kp + 1];
        g_protoH2[ct * 4096 + kp * 256 + ci] = pack_h2(v0, v1);
        g_protoL2[ct * 4096 + kp * 256 + ci] =
            pack_h2(v0 - h2f(v0), v1 - h2f(v1));
    }
}

// ---------------------------------------------------------------------------
// Kernel 3: 3x fp16-split mma.sync(k16) over COMPACTED protos, 128-px tiles
// grid = 32 batches * 32 tiles(128 px) ; 256 threads, 8 warps (2 wm x 4 wn)
// ---------------------------------------------------------------------------
__global__ void __launch_bounds__(256, 2)
dist_kernel(const float* __restrict__ qry, float* __restrict__ out) {
    extern __shared__ __align__(16) float sm[];
    float* SQ = sm + OFF_SQ;
    float* QN = sm + OFF_QN;
    float* RA = sm + OFF_RA;
    int*   RI = (int*)(sm + OFF_RI);
    float* RS = sm + OFF_RS;
    float* RW = sm + OFF_RW;

    int tid = threadIdx.x, w = tid >> 5, l = tid & 31;
    int wm = w & 1, wn = w >> 1;

    const int V = g_vcnt;
    const int nTiles = (V + 15) >> 4;
    const int V16 = nTiles << 4;
    int tmax = (nTiles + 1 - wm) >> 1;
    if (tmax > 4) tmax = 4;

    int b = blockIdx.x >> 5, n0 = (blockIdx.x & 31) << 7;
    const float* Qbase = qry + (size_t)b * 256 * 4096 + n0;

    float acc[4][4][4];
#pragma unroll
    for (int tm = 0; tm < 4; tm++)
#pragma unroll
        for (int tn = 0; tn < 4; tn++)
#pragma unroll
            for (int e = 0; e < 4; e++) acc[tm][tn][e] = 0.f;

    float4 qe0, qe1, qo0, qo1;
    float ssq8[8];
#pragma unroll
    for (int e = 0; e < 8; e++) ssq8[e] = 0.f;
    const int kp0 = tid >> 4, nf = tid & 15;
    const int ka = l & 3, ga = l >> 2;

#define Q_LOAD(ctv)                                                            \
    {                                                                          \
        const float* qc = Qbase + (size_t)((ctv) * 32 + 2 * kp0) * 4096 + nf * 8; \
        qe0 = *(const float4*)(qc);                                            \
        qe1 = *(const float4*)(qc + 4);                                        \
        qo0 = *(const float4*)(qc + 4096);                                     \
        qo1 = *(const float4*)(qc + 4100);                                     \
    }

#define SPLIT_STORE(QHdst, QLdst)                                              \
    {                                                                          \
        float ev[8] = {qe0.x, qe0.y, qe0.z, qe0.w, qe1.x, qe1.y, qe1.z, qe1.w};\
        float od[8] = {qo0.x, qo0.y, qo0.z, qo0.w, qo1.x, qo1.y, qo1.z, qo1.w};\
        uint32_t hq[8], lq[8];                                                 \
        _Pragma("unroll")                                                      \
        for (int e = 0; e < 8; e++) {                                          \
            hq[e] = pack_h2(ev[e], od[e]);                                     \
            lq[e] = pack_h2(ev[e] - h2f(ev[e]), od[e] - h2f(od[e]));           \
            ssq8[e] = fmaf(ev[e], ev[e], fmaf(od[e], od[e], ssq8[e]));         \
        }                                                                      \
        float* hb = (QHdst) + kp0 * QS2 + nf * 8;                              \
        float* lb = (QLdst) + kp0 * QS2 + nf * 8;                              \
        *(uint4*)hb       = make_uint4(hq[0], hq[1], hq[2], hq[3]);            \
        *(uint4*)(hb + 4) = make_uint4(hq[4], hq[5], hq[6], hq[7]);            \
        *(uint4*)lb       = make_uint4(lq[0], lq[1], lq[2], lq[3]);            \
        *(uint4*)(lb + 4) = make_uint4(lq[4], lq[5], lq[6], lq[7]);            \
    }

#define A_LOAD(dstbase, srcH, srcL)                                            \
    _Pragma("unroll")                                                          \
    for (int i = 0; i < 8; i++) {                                              \
        int seg = tid + i * 256;                                               \
        int mat = seg >> 10;                                                   \
        int row = (seg >> 6) & 15, col = (seg & 63) << 2;                      \
        if (col < V16) {                                                       \
            const unsigned* src = (mat ? (srcL) : (srcH)) + row * 256 + col;   \
            cpasync16(s2u((dstbase) + mat * (16 * AS) + row * AS + col), src); \
        }                                                                      \
    }

    // ---- prologue ----
    {
        A_LOAD(sm + OFF_A0, g_protoH2, g_protoL2)
        asm volatile("cp.async.commit_group;" ::: "memory");
        Q_LOAD(0)
        float* QHd = sm + OFF_Q;
        SPLIT_STORE(QHd, QHd + 2112)
        Q_LOAD(1)
    }

    for (int ct = 0; ct < 8; ct++) {
        int stg = ct & 1;
        float* AH = sm + (stg ? OFF_A1 : OFF_A0);
        float* AL = AH + 16 * AS;
        float* QH = sm + OFF_Q + stg * QBUF;
        float* QL = QH + 2112;

        asm volatile("cp.async.wait_group 0;" ::: "memory");
        __syncthreads();

        if (ct < 7) {
            float* AHn = sm + (stg ? OFF_A0 : OFF_A1);
            const unsigned* sH = g_protoH2 + (ct + 1) * 4096;
            const unsigned* sL = g_protoL2 + (ct + 1) * 4096;
            A_LOAD(AHn, sH, sL)
            asm volatile("cp.async.commit_group;" ::: "memory");

            float* QHd = sm + OFF_Q + (stg ^ 1) * QBUF;
            SPLIT_STORE(QHd, QHd + 2112)
            if (ct < 6) Q_LOAD(ct + 2)
        }

#pragma unroll
        for (int ks = 0; ks < 2; ks++) {
            uint32_t bh[4][2], bl[4][2];
            const int qb = (ks * 8 + ka) * QS2 + wn * 32 + ga;
#pragma unroll
            for (int tn = 0; tn < 4; tn++) {
                bh[tn][0] = __float_as_uint(QH[qb + tn * 8]);
                bh[tn][1] = __float_as_uint(QH[qb + tn * 8 + 4 * QS2]);
                bl[tn][0] = __float_as_uint(QL[qb + tn * 8]);
                bl[tn][1] = __float_as_uint(QL[qb + tn * 8 + 4 * QS2]);
            }
            const int ab = (ks * 8 + ka) * AS + wm * 16 + ga;
#pragma unroll
            for (int tm = 0; tm < 4; tm++) {
                if (tm < tmax) {
                    int a0i = ab + tm * 32;
                    uint32_t ah0 = __float_as_uint(AH[a0i]);
                    uint32_t ah1 = __float_as_uint(AH[a0i + 8]);
                    uint32_t ah2 = __float_as_uint(AH[a0i + 4 * AS]);
                    uint32_t ah3 = __float_as_uint(AH[a0i + 4 * AS + 8]);
                    uint32_t al0 = __float_as_uint(AL[a0i]);
                    uint32_t al1 = __float_as_uint(AL[a0i + 8]);
                    uint32_t al2 = __float_as_uint(AL[a0i + 4 * AS]);
                    uint32_t al3 = __float_as_uint(AL[a0i + 4 * AS + 8]);
#pragma unroll
                    for (int tn = 0; tn < 4; tn++) {
                        mma16(acc[tm][tn], ah0, ah1, ah2, ah3, bh[tn][0], bh[tn][1]);
                        mma16(acc[tm][tn], ah0, ah1, ah2, ah3, bl[tn][0], bl[tn][1]);
                        mma16(acc[tm][tn], al0, al1, al2, al3, bh[tn][0], bh[tn][1]);
                    }
                }
            }
        }
    }

    __syncthreads();

    // ---- qnorm reduction (deterministic) ----
    {
        float* sq = SQ + kp0 * 128 + nf * 8;
        *(float4*)sq       = make_float4(ssq8[0], ssq8[1], ssq8[2], ssq8[3]);
        *(float4*)(sq + 4) = make_float4(ssq8[4], ssq8[5], ssq8[6], ssq8[7]);
    }
    __syncthreads();
    if (tid < 128) {
        float s = 0.f;
#pragma unroll
        for (int j = 0; j < 16; j++) s += SQ[j * 128 + tid];
        QN[tid] = 20.0f / fmaxf(sqrtf(s), 1e-4f);
    }
    __syncthreads();

    // ---- two-phase epilogue over 64-px halves, two-sweep softmax ----
    float* dS = sm;
    const float NEG = __int_as_float(0xff800000);
    const int L = (V + 3) >> 2;

    for (int ph = 0; ph < 2; ph++) {
        if ((wn >> 1) == ph) {
            int nbase = (wn & 1) * 32 + 2 * ka;
#pragma unroll
            for (int tm = 0; tm < 4; tm++) {
                if (tm < tmax) {
                    int r = (tm * 2 + wm) * 16 + ga;
#pragma unroll
                    for (int tn = 0; tn < 4; tn++) {
                        int n = nbase + tn * 8;
                        dS[n * DSS + r]           = acc[tm][tn][0];
                        dS[(n + 1) * DSS + r]     = acc[tm][tn][1];
                        dS[n * DSS + r + 8]       = acc[tm][tn][2];
                        dS[(n + 1) * DSS + r + 8] = acc[tm][tn][3];
                    }
                }
            }
        }
        __syncthreads();

        int q = tid >> 6, n = tid & 63;
        float scl = QN[ph * 64 + n];
        int c0 = q * L, c1 = min(c0 + L, V);
        const float* rowp = dS + n * DSS;

        // sweep 1: max + argmax, 4 independent accumulators
        float b0 = NEG, b1 = NEG, b2 = NEG, b3 = NEG;
        int i0 = 0, i1 = 0, i2 = 0, i3 = 0;
        int c = c0;
        for (; c + 4 <= c1; c += 4) {
            float d0 = rowp[c], d1 = rowp[c + 1], d2 = rowp[c + 2], d3 = rowp[c + 3];
            if (d0 > b0) { b0 = d0; i0 = c; }
            if (d1 > b1) { b1 = d1; i1 = c + 1; }
            if (d2 > b2) { b2 = d2; i2 = c + 2; }
            if (d3 > b3) { b3 = d3; i3 = c + 3; }
        }
        for (; c < c1; c++) {
            float d = rowp[c];
            if (d > b0) { b0 = d; i0 = c; }
        }
        float B = b0; int I = i0;
        if (b1 > B || (b1 == B && i1 < I)) { B = b1; I = i1; }
        if (b2 > B || (b2 == B && i2 < I)) { B = b2; I = i2; }
        if (b3 > B || (b3 == B && i3 < I)) { B = b3; I = i3; }
        float mx = B * scl;

        // sweep 2: branch-free exp + weighted sums, 4-way ILP
        float s0 = 0.f, s1 = 0.f, s2 = 0.f, s3 = 0.f;
        float w0 = 0.f, w1 = 0.f, w2 = 0.f, w3 = 0.f;
        c = c0;
        for (; c + 4 <= c1; c += 4) {
            float d0 = rowp[c] * scl, d1 = rowp[c + 1] * scl;
            float d2 = rowp[c + 2] * scl, d3 = rowp[c + 3] * scl;
            float e0 = __expf(d0 - mx), e1 = __expf(d1 - mx);
            float e2 = __expf(d2 - mx), e3 = __expf(d3 - mx);
            s0 += e0; w0 = fmaf(e0, d0, w0);
            s1 += e1; w1 = fmaf(e1, d1, w1);
            s2 += e2; w2 = fmaf(e2, d2, w2);
            s3 += e3; w3 = fmaf(e3, d3, w3);
        }
        for (; c < c1; c++) {
            float d = rowp[c] * scl;
            float e = __expf(d - mx);
            s0 += e; w0 = fmaf(e, d, w0);
        }
        float se = (s0 + s1) + (s2 + s3);
        float ws = (w0 + w1) + (w2 + w3);

        RA[q * 64 + n] = (c1 > c0) ? mx : NEG;
        RI[q * 64 + n] = __ldg(&g_map[I]);
        RS[q * 64 + n] = se;
        RW[q * 64 + n] = ws;
        __syncthreads();

        if (tid < 64) {
            float Bm = NEG, SE = 0.f, WS = 0.f; int Im = 0;
#pragma unroll
            for (int qq = 0; qq < 4; qq++) {
                float bq = RA[qq * 64 + tid];
                float sq = RS[qq * 64 + tid], wq = RW[qq * 64 + tid];
                if (bq > Bm) {
                    float r = (Bm == NEG) ? 0.f : __expf(Bm - bq);
                    SE = SE * r + sq; WS = WS * r + wq;
                    Bm = bq; Im = RI[qq * 64 + tid];
                } else {
                    float r = (bq == NEG) ? 0.f : __expf(bq - Bm);
                    SE += sq * r; WS += wq * r;
                }
            }
            size_t o = (size_t)b * 4096 + n0 + ph * 64 + tid;
            out[o] = WS / SE;
            out[131072 + o] = (float)Im;
        }
        __syncthreads();
    }
}

extern "C" void kernel_launch(void* const* d_in, const int* in_sizes, int n_in,
                              void* d_out, int out_size) {
    const float* qry   = (const float*)d_in[0];
    const float* sup_x = (const float*)d_in[1];
    const float* sup_y = (const float*)d_in[2];
    float* out = (float*)d_out;

    cudaFuncSetAttribute(dist_kernel,
                         cudaFuncAttributeMaxDynamicSharedMemorySize, SMEM_BYTES);

    proto_kernel<<<256, 256>>>(sup_x, sup_y);
    scan_kernel<<<1, 256>>>();
    pack_kernel<<<256, 128>>>(sup_y, out);
    dist_kernel<<<1024, 256, SMEM_BYTES>>>(qry, out);
}